// round 12
// baseline (speedup 1.0000x reference)
#include <cuda_runtime.h>
#include <cuda_fp16.h>
#include <cstdint>

#define NB    8
#define NC    512
#define NL    2048
#define NH    8
#define ND    64
#define NHID  512
#define NOQKV 1536

// ---------------- device-global scratch (allocation-free) ----------------
__device__ __half g_xh[(size_t)NB * NC * NL];
__device__ __half g_xl[(size_t)NB * NC * NL];
__device__ __half g_wqh[(size_t)NC * NOQKV];    // [c][m] transposed
__device__ __half g_wql[(size_t)NC * NOQKV];
__device__ __half g_woh[(size_t)NHID * NC];     // [c][m] transposed
__device__ __half g_wol[(size_t)NHID * NC];
__device__ __half g_qkvh[(size_t)NB * NOQKV * NL];
__device__ __half g_qkvl[(size_t)NB * NOQKV * NL];
__device__ __half g_atth[(size_t)NB * NHID * NL];
__device__ __half g_attl[(size_t)NB * NHID * NL];

__device__ __forceinline__ float ex2(float x) {
    float y; asm("ex2.approx.f32 %0, %1;" : "=f"(y) : "f"(x)); return y;
}
// pack two fp32 -> f16x2 {low half = first arg}
__device__ __forceinline__ unsigned pckhf(float lo, float hi) {
    unsigned r; asm("cvt.rn.f16x2.f32 %0, %1, %2;" : "=r"(r) : "f"(hi), "f"(lo)); return r;
}
// fp32 -> fp16 -> fp32 round trip (the "hi" part)
__device__ __forceinline__ float hfrt(float x) {
    float r;
    asm("{.reg .b16 t; cvt.rn.f16.f32 t, %1; cvt.f32.f16 %0, t;}" : "=f"(r) : "f"(x));
    return r;
}
// merge an f16x2 pair into two fp32 accumulators
__device__ __forceinline__ void mergeh(float& a, float& b, unsigned u) {
    asm("{\n\t.reg .b16 l,h;\n\t.reg .f32 x,y;\n\t"
        "mov.b32 {l,h}, %2;\n\t"
        "cvt.f32.f16 x, l;\n\tcvt.f32.f16 y, h;\n\t"
        "add.f32 %0, %0, x;\n\tadd.f32 %1, %1, y;\n\t}"
        : "+f"(a), "+f"(b) : "r"(u));
}
__device__ __forceinline__ void cpa16(unsigned s, const void* g) {
    asm volatile("cp.async.cg.shared.global [%0], [%1], 16;" :: "r"(s), "l"(g));
}
#define CPCOMMIT() asm volatile("cp.async.commit_group;")
#define CPWAIT(n)  asm volatile("cp.async.wait_group %0;" :: "n"(n))

#define LDSMX4(R0,R1,R2,R3,A) \
    asm volatile("ldmatrix.sync.aligned.m8n8.x4.shared.b16 {%0,%1,%2,%3}, [%4];" \
        : "=r"(R0),"=r"(R1),"=r"(R2),"=r"(R3) : "r"(A))
#define LDSMX4T(R0,R1,R2,R3,A) \
    asm volatile("ldmatrix.sync.aligned.m8n8.x4.trans.shared.b16 {%0,%1,%2,%3}, [%4];" \
        : "=r"(R0),"=r"(R1),"=r"(R2),"=r"(R3) : "r"(A))
// fp16 inputs, fp32 accumulate (the hi*hi pass)
#define MMAH32(C,A0,A1,A2,A3,B0,B1) \
    asm("mma.sync.aligned.m16n8k16.row.col.f32.f16.f16.f32 " \
        "{%0,%1,%2,%3},{%4,%5,%6,%7},{%8,%9},{%0,%1,%2,%3};" \
        : "+f"((C)[0]),"+f"((C)[1]),"+f"((C)[2]),"+f"((C)[3]) \
        : "r"(A0),"r"(A1),"r"(A2),"r"(A3),"r"(B0),"r"(B1))
// fp16 inputs, fp16 accumulate (the small cross-term passes)
#define MMAH16(C,A0,A1,A2,A3,B0,B1) \
    asm("mma.sync.aligned.m16n8k16.row.col.f16.f16.f16.f16 " \
        "{%0,%1},{%2,%3,%4,%5},{%6,%7},{%0,%1};" \
        : "+r"((C)[0]),"+r"((C)[1]) \
        : "r"(A0),"r"(A1),"r"(A2),"r"(A3),"r"(B0),"r"(B1))

// ---------------------------------------------------------------------------
// fp32 -> fp16 hi/lo split passes
// ---------------------------------------------------------------------------
__global__ void cvt_split(const float4* __restrict__ src,
                          uint2* __restrict__ h, uint2* __restrict__ l)
{
    int i = blockIdx.x * blockDim.x + threadIdx.x;
    float4 f = src[i];
    uint2 hv, lv;
    hv.x = pckhf(f.x, f.y);
    hv.y = pckhf(f.z, f.w);
    lv.x = pckhf(f.x - hfrt(f.x), f.y - hfrt(f.y));
    lv.y = pckhf(f.z - hfrt(f.z), f.w - hfrt(f.w));
    h[i] = hv; l[i] = lv;
}

__global__ void cvt_splitT(const float* __restrict__ w,
                           __half* __restrict__ ht,
                           __half* __restrict__ lt, int M, int C)
{
    int idx = blockIdx.x * blockDim.x + threadIdx.x;
    int m = idx / C, c = idx % C;
    float v = w[idx];
    float hi = hfrt(v);
    ht[(size_t)c * M + m] = __float2half(hi);
    lt[(size_t)c * M + m] = __float2half(v - hi);
}

// ---------------------------------------------------------------------------
// fp16 split-MMA GEMM, 3-stage cp.async pipeline.
// Block 128x128, ktile 32, 256 threads = 8 warps (2x4), 64m x 32n per warp.
// hi*hi -> fp32 acc; hi*lo + lo*hi -> fp16 acc, merged once in the epilogue.
// ---------------------------------------------------------------------------
#define GSTG 34816   // bytes per stage: 4 arrays x 32 x 136 x 2B

template<int M, int K, bool HAS_BIAS, bool SPLIT_OUT>
__global__ __launch_bounds__(256) void gemm_h(
    const __half* __restrict__ Ah_g, const __half* __restrict__ Al_g,
    const __half* __restrict__ Bh_g, const __half* __restrict__ Bl_g,
    const float* __restrict__ bias,
    __half* __restrict__ Yh, __half* __restrict__ Yl,
    float* __restrict__ Yf)
{
    extern __shared__ __align__(16) unsigned char smg[];
    const int NT = K / 32;

    const int b  = blockIdx.z;
    const int m0 = blockIdx.y * 128;
    const int n0 = blockIdx.x * 128;

    const int tid  = threadIdx.x;
    const int lane = tid & 31;
    const int warp = tid >> 5;
    const int wm   = warp >> 2;          // m offset wm*64
    const int wn   = warp & 3;           // n offset wn*32

    unsigned sb = (unsigned)__cvta_generic_to_shared(smg);

    const unsigned offA = ((((lane >> 4) & 1) * 8 + (lane & 7)) * 272)
                        + (wm * 64 + ((lane >> 3) & 1) * 8) * 2;
    const unsigned offB = ((((lane >> 3) & 1) * 8 + (lane & 7)) * 272)
                        + (wn * 32 + ((lane >> 4) & 1) * 8) * 2;

    const int r0c = tid >> 4, c0c = (tid & 15) * 8;
    const int r1c = (tid + 256) >> 4, c1c = ((tid + 256) & 15) * 8;

    float acc[4][4][4];
    unsigned cacc[4][4][2];
    #pragma unroll
    for (int i = 0; i < 4; i++)
        #pragma unroll
        for (int j = 0; j < 4; j++) {
            acc[i][j][0] = acc[i][j][1] = acc[i][j][2] = acc[i][j][3] = 0.0f;
            cacc[i][j][0] = 0u; cacc[i][j][1] = 0u;
        }

    auto issue = [&](int kt, int st) {
        unsigned base = sb + st * GSTG;
        int k0 = kt * 32;
        {
            size_t ga = (size_t)(k0 + r0c) * M + m0 + c0c;
            size_t gb = ((size_t)b * K + k0 + r0c) * NL + n0 + c0c;
            unsigned so = r0c * 272 + c0c * 2;
            cpa16(base + so,          Ah_g + ga);
            cpa16(base + 8704 + so,   Al_g + ga);
            cpa16(base + 17408 + so,  Bh_g + gb);
            cpa16(base + 26112 + so,  Bl_g + gb);
        }
        {
            size_t ga = (size_t)(k0 + r1c) * M + m0 + c1c;
            size_t gb = ((size_t)b * K + k0 + r1c) * NL + n0 + c1c;
            unsigned so = r1c * 272 + c1c * 2;
            cpa16(base + so,          Ah_g + ga);
            cpa16(base + 8704 + so,   Al_g + ga);
            cpa16(base + 17408 + so,  Bh_g + gb);
            cpa16(base + 26112 + so,  Bl_g + gb);
        }
    };

    issue(0, 0); CPCOMMIT();
    issue(1, 1); CPCOMMIT();

    for (int kt = 0; kt < NT; kt++) {
        CPWAIT(1);
        __syncthreads();
        if (kt + 2 < NT) issue(kt + 2, (kt + 2) % 3);
        CPCOMMIT();

        unsigned base = sb + (kt % 3) * GSTG;
        const unsigned SAH = base, SAL = base + 8704,
                       SBH = base + 17408, SBL = base + 26112;

        #pragma unroll
        for (int kc = 0; kc < 2; kc++) {
            unsigned kb = kc * 16 * 272;
            unsigned bh[2][4], bl[2][4];
            LDSMX4T(bh[0][0], bh[0][1], bh[0][2], bh[0][3], SBH + offB + kb);
            LDSMX4T(bh[1][0], bh[1][1], bh[1][2], bh[1][3], SBH + offB + kb + 32);
            LDSMX4T(bl[0][0], bl[0][1], bl[0][2], bl[0][3], SBL + offB + kb);
            LDSMX4T(bl[1][0], bl[1][1], bl[1][2], bl[1][3], SBL + offB + kb + 32);
            #pragma unroll
            for (int mf = 0; mf < 4; mf++) {
                unsigned ah0,ah1,ah2,ah3, al0,al1,al2,al3;
                LDSMX4T(ah0,ah1,ah2,ah3, SAH + offA + kb + mf * 32);
                LDSMX4T(al0,al1,al2,al3, SAL + offA + kb + mf * 32);
                // pass 1: hi*hi (fp32 acc)
                #pragma unroll
                for (int g = 0; g < 4; g++)
                    MMAH32(acc[mf][g], ah0,ah1,ah2,ah3,
                           bh[g >> 1][(g & 1) * 2], bh[g >> 1][(g & 1) * 2 + 1]);
                // pass 2: hi*lo (fp16 acc)
                #pragma unroll
                for (int g = 0; g < 4; g++)
                    MMAH16(cacc[mf][g], ah0,ah1,ah2,ah3,
                           bl[g >> 1][(g & 1) * 2], bl[g >> 1][(g & 1) * 2 + 1]);
                // pass 3: lo*hi (fp16 acc)
                #pragma unroll
                for (int g = 0; g < 4; g++)
                    MMAH16(cacc[mf][g], al0,al1,al2,al3,
                           bh[g >> 1][(g & 1) * 2], bh[g >> 1][(g & 1) * 2 + 1]);
            }
        }
    }

    // ---- merge cross terms, then epilogue ----
    #pragma unroll
    for (int mf = 0; mf < 4; mf++)
        #pragma unroll
        for (int g = 0; g < 4; g++) {
            mergeh(acc[mf][g][0], acc[mf][g][1], cacc[mf][g][0]);
            mergeh(acc[mf][g][2], acc[mf][g][3], cacc[mf][g][1]);
        }

    const int r0 = lane >> 2;
    const int cp = (lane & 3) * 2;
    #pragma unroll
    for (int mf = 0; mf < 4; mf++) {
        int ml = m0 + wm * 64 + mf * 16 + r0;
        float bv0 = 0.0f, bv1 = 0.0f;
        if (HAS_BIAS) { bv0 = bias[ml]; bv1 = bias[ml + 8]; }
        #pragma unroll
        for (int g = 0; g < 4; g++) {
            int n = n0 + wn * 32 + (g >> 1) * 16 + (g & 1) * 8 + cp;
            float* c = acc[mf][g];
            size_t a0 = ((size_t)b * M + ml) * NL + n;
            size_t a1 = a0 + (size_t)8 * NL;
            if (SPLIT_OUT) {
                *(unsigned*)(Yh + a0) = pckhf(c[0], c[1]);
                *(unsigned*)(Yl + a0) = pckhf(c[0] - hfrt(c[0]), c[1] - hfrt(c[1]));
                *(unsigned*)(Yh + a1) = pckhf(c[2], c[3]);
                *(unsigned*)(Yl + a1) = pckhf(c[2] - hfrt(c[2]), c[3] - hfrt(c[3]));
            } else {
                *(float2*)(Yf + a0) = make_float2(c[0] + bv0, c[1] + bv0);
                *(float2*)(Yf + a1) = make_float2(c[2] + bv1, c[3] + bv1);
            }
        }
    }
}

// ---------------------------------------------------------------------------
// Flash attention: BM=128 queries, 4 warps x m32 rows, BN=64 keys,
// 2-stage cp.async K/V pipeline. hi*hi fp32-acc; cross terms fp16-acc,
// merged per tile (S before softmax; O at end of each j-tile).
// ---------------------------------------------------------------------------
#define ASTG 36864

__global__ __launch_bounds__(128) void attn_kernel(
    const __half* __restrict__ qkvh, const __half* __restrict__ qkvl,
    __half* __restrict__ atth, __half* __restrict__ attl)
{
    extern __shared__ __align__(16) unsigned char sma[];

    const int tid  = threadIdx.x;
    const int lane = tid & 31;
    const int warp = tid >> 5;
    const int i0 = blockIdx.x * 128;
    const int h  = blockIdx.y;
    const int b  = blockIdx.z;

    const size_t base = ((size_t)b * NOQKV + h * ND) * NL;
    const __half* qph = qkvh + base;
    const __half* qpl = qkvl + base;
    const __half* kph = qph + (size_t)NHID * NL;
    const __half* kpl = qpl + (size_t)NHID * NL;
    const __half* vph = qph + (size_t)2 * NHID * NL;
    const __half* vpl = qpl + (size_t)2 * NHID * NL;

    unsigned sb = (unsigned)__cvta_generic_to_shared(sma);
    const unsigned QH = sb, QL = sb + 17408, KV0 = sb + 34816;

    const unsigned offQ = (((lane >> 4) & 1) * 8 + (lane & 7)) * 272
                        + (warp * 32 + ((lane >> 3) & 1) * 8) * 2;
    const unsigned offK = (((lane >> 3) & 1) * 8 + (lane & 7)) * 144
                        + (((lane >> 4) & 1) * 8) * 2;
    const unsigned offV = (((lane >> 4) & 1) * 8 + (lane & 7)) * 144
                        + (((lane >> 3) & 1) * 8) * 2;

    const float SC = 0.125f * 1.44269504f;

    auto issueKV = [&](int j0, int st) {
        unsigned kb = KV0 + st * ASTG;
        #pragma unroll
        for (int p = 0; p < 4; p++) {
            int q   = tid + p * 128;
            int row = q >> 3;
            int col = (q & 7) * 8;
            unsigned so = row * 144 + col * 2;
            size_t g = (size_t)row * NL + j0 + col;
            cpa16(kb + so,          kph + g);
            cpa16(kb + 9216 + so,   kpl + g);
            cpa16(kb + 18432 + so,  vph + g);
            cpa16(kb + 27648 + so,  vpl + g);
        }
    };

    {
        #pragma unroll
        for (int p = 0; p < 8; p++) {
            int q = tid + p * 128;
            int r = q >> 4, c16 = (q & 15) * 8;
            unsigned so = r * 272 + c16 * 2;
            size_t g = (size_t)r * NL + i0 + c16;
            cpa16(QH + so, qph + g);
            cpa16(QL + so, qpl + g);
        }
        issueKV(0, 0);
        CPCOMMIT();
    }

    float o[2][8][4];
    float mm[2][2], ll[2][2];
    #pragma unroll
    for (int mb = 0; mb < 2; mb++) {
        mm[mb][0] = -1e30f; mm[mb][1] = -1e30f;
        ll[mb][0] = 0.0f;   ll[mb][1] = 0.0f;
        #pragma unroll
        for (int t = 0; t < 8; t++)
            #pragma unroll
            for (int c = 0; c < 4; c++) o[mb][t][c] = 0.0f;
    }

    for (int jt = 0; jt < 32; jt++) {
        if (jt + 1 < 32) issueKV((jt + 1) * 64, (jt + 1) & 1);
        CPCOMMIT();
        if (jt == 31) { CPWAIT(0); } else { CPWAIT(1); }
        __syncthreads();

        unsigned kb = KV0 + (jt & 1) * ASTG;
        const unsigned KH = kb, KL = kb + 9216, VH = kb + 18432, VL = kb + 27648;

        // ---- S = Q K^T : hi*hi fp32 acc, cross terms fp16 acc ----
        float s[2][8][4];
        unsigned sc[2][8][2];
        #pragma unroll
        for (int mb = 0; mb < 2; mb++)
            #pragma unroll
            for (int t = 0; t < 8; t++) {
                s[mb][t][0] = s[mb][t][1] = s[mb][t][2] = s[mb][t][3] = 0.0f;
                sc[mb][t][0] = 0u; sc[mb][t][1] = 0u;
            }

        #pragma unroll
        for (int kc = 0; kc < 4; kc++) {
            unsigned kcq = kc * 16 * 272;
            unsigned kck = kc * 16 * 144;
            unsigned qa[2][4], qe[2][4];
            LDSMX4T(qa[0][0],qa[0][1],qa[0][2],qa[0][3], QH + offQ + kcq);
            LDSMX4T(qa[1][0],qa[1][1],qa[1][2],qa[1][3], QH + offQ + kcq + 32);
            LDSMX4T(qe[0][0],qe[0][1],qe[0][2],qe[0][3], QL + offQ + kcq);
            LDSMX4T(qe[1][0],qe[1][1],qe[1][2],qe[1][3], QL + offQ + kcq + 32);
            #pragma unroll
            for (int p = 0; p < 4; p++) {
                unsigned nb = p * 32;
                unsigned h0,h1,h2,h3, e0,e1,e2,e3;
                LDSMX4T(h0,h1,h2,h3, KH + offK + kck + nb);
                LDSMX4T(e0,e1,e2,e3, KL + offK + kck + nb);
                #pragma unroll
                for (int mb = 0; mb < 2; mb++) {
                    MMAH32(s[mb][2*p],   qa[mb][0],qa[mb][1],qa[mb][2],qa[mb][3], h0,h1);
                    MMAH32(s[mb][2*p+1], qa[mb][0],qa[mb][1],qa[mb][2],qa[mb][3], h2,h3);
                }
                #pragma unroll
                for (int mb = 0; mb < 2; mb++) {
                    MMAH16(sc[mb][2*p],   qa[mb][0],qa[mb][1],qa[mb][2],qa[mb][3], e0,e1);
                    MMAH16(sc[mb][2*p+1], qa[mb][0],qa[mb][1],qa[mb][2],qa[mb][3], e2,e3);
                }
                #pragma unroll
                for (int mb = 0; mb < 2; mb++) {
                    MMAH16(sc[mb][2*p],   qe[mb][0],qe[mb][1],qe[mb][2],qe[mb][3], h0,h1);
                    MMAH16(sc[mb][2*p+1], qe[mb][0],qe[mb][1],qe[mb][2],qe[mb][3], h2,h3);
                }
            }
        }

        // merge cross terms into S
        #pragma unroll
        for (int mb = 0; mb < 2; mb++)
            #pragma unroll
            for (int t = 0; t < 8; t++) {
                mergeh(s[mb][t][0], s[mb][t][1], sc[mb][t][0]);
                mergeh(s[mb][t][2], s[mb][t][3], sc[mb][t][1]);
            }

        // ---- online softmax + P fragments per mb ----
        unsigned pah[2][4][4], pal[2][4][4];
        #pragma unroll
        for (int mb = 0; mb < 2; mb++) {
            float mx0 = -1e30f, mx1 = -1e30f;
            #pragma unroll
            for (int t = 0; t < 8; t++) {
                s[mb][t][0] *= SC; s[mb][t][1] *= SC;
                s[mb][t][2] *= SC; s[mb][t][3] *= SC;
                mx0 = fmaxf(mx0, fmaxf(s[mb][t][0], s[mb][t][1]));
                mx1 = fmaxf(mx1, fmaxf(s[mb][t][2], s[mb][t][3]));
            }
            mx0 = fmaxf(mx0, __shfl_xor_sync(0xffffffffu, mx0, 1));
            mx0 = fmaxf(mx0, __shfl_xor_sync(0xffffffffu, mx0, 2));
            mx1 = fmaxf(mx1, __shfl_xor_sync(0xffffffffu, mx1, 1));
            mx1 = fmaxf(mx1, __shfl_xor_sync(0xffffffffu, mx1, 2));
            float mn0 = fmaxf(mm[mb][0], mx0), mn1 = fmaxf(mm[mb][1], mx1);
            float c0 = ex2(mm[mb][0] - mn0),   c1 = ex2(mm[mb][1] - mn1);
            mm[mb][0] = mn0; mm[mb][1] = mn1;

            float rs0 = 0.0f, rs1 = 0.0f;
            #pragma unroll
            for (int t = 0; t < 8; t++) {
                s[mb][t][0] = ex2(s[mb][t][0] - mn0);
                s[mb][t][1] = ex2(s[mb][t][1] - mn0);
                s[mb][t][2] = ex2(s[mb][t][2] - mn1);
                s[mb][t][3] = ex2(s[mb][t][3] - mn1);
                rs0 += s[mb][t][0] + s[mb][t][1];
                rs1 += s[mb][t][2] + s[mb][t][3];
            }
            ll[mb][0] = ll[mb][0] * c0 + rs0;
            ll[mb][1] = ll[mb][1] * c1 + rs1;
            #pragma unroll
            for (int t = 0; t < 8; t++) {
                o[mb][t][0] *= c0; o[mb][t][1] *= c0;
                o[mb][t][2] *= c1; o[mb][t][3] *= c1;
            }
            #pragma unroll
            for (int c = 0; c < 4; c++) {
                int A = 2 * c, B = 2 * c + 1;
                pah[mb][c][0] = pckhf(s[mb][A][0], s[mb][A][1]);
                pah[mb][c][1] = pckhf(s[mb][A][2], s[mb][A][3]);
                pah[mb][c][2] = pckhf(s[mb][B][0], s[mb][B][1]);
                pah[mb][c][3] = pckhf(s[mb][B][2], s[mb][B][3]);
                pal[mb][c][0] = pckhf(s[mb][A][0]-hfrt(s[mb][A][0]), s[mb][A][1]-hfrt(s[mb][A][1]));
                pal[mb][c][1] = pckhf(s[mb][A][2]-hfrt(s[mb][A][2]), s[mb][A][3]-hfrt(s[mb][A][3]));
                pal[mb][c][2] = pckhf(s[mb][B][0]-hfrt(s[mb][B][0]), s[mb][B][1]-hfrt(s[mb][B][1]));
                pal[mb][c][3] = pckhf(s[mb][B][2]-hfrt(s[mb][B][2]), s[mb][B][3]-hfrt(s[mb][B][3]));
            }
        }

        // ---- O += P V : hi*hi fp32 acc; cross fp16 acc merged per jt ----
        unsigned oc[2][8][2];
        #pragma unroll
        for (int mb = 0; mb < 2; mb++)
            #pragma unroll
            for (int t = 0; t < 8; t++) { oc[mb][t][0] = 0u; oc[mb][t][1] = 0u; }

        #pragma unroll
        for (int c = 0; c < 4; c++) {
            unsigned jb = c * 32;
            #pragma unroll
            for (int p = 0; p < 4; p++) {
                unsigned db = p * 2304;
                unsigned h0,h1,h2,h3, e0,e1,e2,e3;
                LDSMX4(h0,h1,h2,h3, VH + offV + db + jb);
                LDSMX4(e0,e1,e2,e3, VL + offV + db + jb);
                #pragma unroll
                for (int mb = 0; mb < 2; mb++) {
                    MMAH32(o[mb][2*p],   pah[mb][c][0],pah[mb][c][1],pah[mb][c][2],pah[mb][c][3], h0,h1);
                    MMAH32(o[mb][2*p+1], pah[mb][c][0],pah[mb][c][1],pah[mb][c][2],pah[mb][c][3], h2,h3);
                }
                #pragma unroll
                for (int mb = 0; mb < 2; mb++) {
                    MMAH16(oc[mb][2*p],   pah[mb][c][0],pah[mb][c][1],pah[mb][c][2],pah[mb][c][3], e0,e1);
                    MMAH16(oc[mb][2*p+1], pah[mb][c][0],pah[mb][c][1],pah[mb][c][2],pah[mb][c][3], e2,e3);
                }
                #pragma unroll
                for (int mb = 0; mb < 2; mb++) {
                    MMAH16(oc[mb][2*p],   pal[mb][c][0],pal[mb][c][1],pal[mb][c][2],pal[mb][c][3], h0,h1);
                    MMAH16(oc[mb][2*p+1], pal[mb][c][0],pal[mb][c][1],pal[mb][c][2],pal[mb][c][3], h2,h3);
                }
            }
        }

        #pragma unroll
        for (int mb = 0; mb < 2; mb++)
            #pragma unroll
            for (int t = 0; t < 8; t++) {
                mergeh(o[mb][t][0], o[mb][t][1], oc[mb][t][0]);
                mergeh(o[mb][t][2], o[mb][t][3], oc[mb][t][1]);
            }
        __syncthreads();
    }

    // ---- finalize: write att split [ch][l] ----
    const size_t ob = ((size_t)b * NHID + h * ND) * NL;
    #pragma unroll
    for (int mb = 0; mb < 2; mb++) {
        float l0 = ll[mb][0], l1 = ll[mb][1];
        l0 += __shfl_xor_sync(0xffffffffu, l0, 1);
        l0 += __shfl_xor_sync(0xffffffffu, l0, 2);
        l1 += __shfl_xor_sync(0xffffffffu, l1, 1);
        l1 += __shfl_xor_sync(0xffffffffu, l1, 2);
        float inv0 = __fdividef(1.0f, l0);
        float inv1 = __fdividef(1.0f, l1);

        int ig = i0 + warp * 32 + mb * 16 + (lane >> 2);
        #pragma unroll
        for (int dt = 0; dt < 8; dt++) {
            int d = dt * 8 + (lane & 3) * 2;
            float v0 = o[mb][dt][0] * inv0, v1 = o[mb][dt][1] * inv0;
            float v2 = o[mb][dt][2] * inv1, v3 = o[mb][dt][3] * inv1;
            size_t a0 = ob + (size_t)d * NL + ig;
            size_t a1 = ob + (size_t)(d + 1) * NL + ig;
            atth[a0]     = __float2half(v0);
            attl[a0]     = __float2half(v0 - hfrt(v0));
            atth[a1]     = __float2half(v1);
            attl[a1]     = __float2half(v1 - hfrt(v1));
            atth[a0 + 8] = __float2half(v2);
            attl[a0 + 8] = __float2half(v2 - hfrt(v2));
            atth[a1 + 8] = __float2half(v3);
            attl[a1 + 8] = __float2half(v3 - hfrt(v3));
        }
    }
}

// ---------------------------------------------------------------------------
extern "C" void kernel_launch(void* const* d_in, const int* in_sizes, int n_in,
                              void* d_out, int out_size)
{
    const float* x     = (const float*)d_in[0];
    const float* w_qkv = (const float*)d_in[1];
    const float* w_out = (const float*)d_in[2];
    const float* b_out = (const float*)d_in[3];
    float* out = (float*)d_out;

    __half *xh, *xl, *wqh, *wql, *woh, *wol, *qkvh, *qkvl, *atth, *attl;
    cudaGetSymbolAddress((void**)&xh,   g_xh);
    cudaGetSymbolAddress((void**)&xl,   g_xl);
    cudaGetSymbolAddress((void**)&wqh,  g_wqh);
    cudaGetSymbolAddress((void**)&wql,  g_wql);
    cudaGetSymbolAddress((void**)&woh,  g_woh);
    cudaGetSymbolAddress((void**)&wol,  g_wol);
    cudaGetSymbolAddress((void**)&qkvh, g_qkvh);
    cudaGetSymbolAddress((void**)&qkvl, g_qkvl);
    cudaGetSymbolAddress((void**)&atth, g_atth);
    cudaGetSymbolAddress((void**)&attl, g_attl);

    // 0) split inputs/weights
    cvt_split<<<(NB * NC * NL / 4) / 256, 256>>>(
        (const float4*)x, (uint2*)xh, (uint2*)xl);
    cvt_splitT<<<(NOQKV * NC) / 256, 256>>>(w_qkv, wqh, wql, NOQKV, NC);
    cvt_splitT<<<(NC * NHID) / 256, 256>>>(w_out, woh, wol, NC, NHID);

    const int gsmem = 3 * GSTG;            // 104448
    const int asmem = 34816 + 2 * ASTG;    // 108544

    // 1) QKV projection
    cudaFuncSetAttribute(gemm_h<NOQKV, NC, false, true>,
                         cudaFuncAttributeMaxDynamicSharedMemorySize, gsmem);
    gemm_h<NOQKV, NC, false, true>
        <<<dim3(NL / 128, NOQKV / 128, NB), 256, gsmem>>>(
            wqh, wql, xh, xl, nullptr, qkvh, qkvl, nullptr);

    // 2) Attention
    cudaFuncSetAttribute(attn_kernel,
                         cudaFuncAttributeMaxDynamicSharedMemorySize, asmem);
    attn_kernel<<<dim3(NL / 128, NH, NB), 128, asmem>>>(qkvh, qkvl, atth, attl);

    // 3) Output projection + bias
    cudaFuncSetAttribute(gemm_h<NC, NHID, true, false>,
                         cudaFuncAttributeMaxDynamicSharedMemorySize, gsmem);
    gemm_h<NC, NHID, true, false>
        <<<dim3(NL / 128, NC / 128, NB), 256, gsmem>>>(
            woh, wol, atth, attl, b_out, nullptr, nullptr, out);
}

// round 13
// speedup vs baseline: 1.1981x; 1.1981x over previous
#include <cuda_runtime.h>
#include <cuda_fp16.h>
#include <cstdint>

#define NB    8
#define NC    512
#define NL    2048
#define NH    8
#define ND    64
#define NHID  512
#define NOQKV 1536

// ---------------- device-global scratch (allocation-free) ----------------
__device__ __half g_xh[(size_t)NB * NC * NL];
__device__ __half g_xl[(size_t)NB * NC * NL];
__device__ __half g_wqh[(size_t)NC * NOQKV];    // [c][m] transposed
__device__ __half g_wql[(size_t)NC * NOQKV];
__device__ __half g_woh[(size_t)NHID * NC];     // [c][m] transposed
__device__ __half g_wol[(size_t)NHID * NC];
__device__ __half g_qkvh[(size_t)NB * NOQKV * NL];
__device__ __half g_qkvl[(size_t)NB * NOQKV * NL];
__device__ __half g_atth[(size_t)NB * NHID * NL];
__device__ __half g_attl[(size_t)NB * NHID * NL];

__device__ __forceinline__ float ex2(float x) {
    float y; asm("ex2.approx.f32 %0, %1;" : "=f"(y) : "f"(x)); return y;
}
// pack two fp32 -> f16x2 {low half = first arg}
__device__ __forceinline__ unsigned pckhf(float lo, float hi) {
    unsigned r; asm("cvt.rn.f16x2.f32 %0, %1, %2;" : "=r"(r) : "f"(hi), "f"(lo)); return r;
}
// fp32 -> fp16 -> fp32 round trip
__device__ __forceinline__ float hfrt(float x) {
    float r;
    asm("{.reg .b16 t; cvt.rn.f16.f32 t, %1; cvt.f32.f16 %0, t;}" : "=f"(r) : "f"(x));
    return r;
}
__device__ __forceinline__ void cpa16(unsigned s, const void* g) {
    asm volatile("cp.async.cg.shared.global [%0], [%1], 16;" :: "r"(s), "l"(g));
}
#define CPCOMMIT() asm volatile("cp.async.commit_group;")
#define CPWAIT(n)  asm volatile("cp.async.wait_group %0;" :: "n"(n))

#define LDSMX4(R0,R1,R2,R3,A) \
    asm volatile("ldmatrix.sync.aligned.m8n8.x4.shared.b16 {%0,%1,%2,%3}, [%4];" \
        : "=r"(R0),"=r"(R1),"=r"(R2),"=r"(R3) : "r"(A))
#define LDSMX4T(R0,R1,R2,R3,A) \
    asm volatile("ldmatrix.sync.aligned.m8n8.x4.trans.shared.b16 {%0,%1,%2,%3}, [%4];" \
        : "=r"(R0),"=r"(R1),"=r"(R2),"=r"(R3) : "r"(A))
// fp16 inputs, fp32 accumulate
#define MMAH(C,A0,A1,A2,A3,B0,B1) \
    asm("mma.sync.aligned.m16n8k16.row.col.f32.f16.f16.f32 " \
        "{%0,%1,%2,%3},{%4,%5,%6,%7},{%8,%9},{%0,%1,%2,%3};" \
        : "+f"((C)[0]),"+f"((C)[1]),"+f"((C)[2]),"+f"((C)[3]) \
        : "r"(A0),"r"(A1),"r"(A2),"r"(A3),"r"(B0),"r"(B1))

// ---------------------------------------------------------------------------
// fp32 -> fp16 hi/lo split passes
// ---------------------------------------------------------------------------
__global__ void cvt_split(const float4* __restrict__ src,
                          uint2* __restrict__ h, uint2* __restrict__ l)
{
    int i = blockIdx.x * blockDim.x + threadIdx.x;
    float4 f = src[i];
    uint2 hv, lv;
    hv.x = pckhf(f.x, f.y);
    hv.y = pckhf(f.z, f.w);
    lv.x = pckhf(f.x - hfrt(f.x), f.y - hfrt(f.y));
    lv.y = pckhf(f.z - hfrt(f.z), f.w - hfrt(f.w));
    h[i] = hv; l[i] = lv;
}

__global__ void cvt_splitT(const float* __restrict__ w,
                           __half* __restrict__ ht,
                           __half* __restrict__ lt, int M, int C)
{
    int idx = blockIdx.x * blockDim.x + threadIdx.x;
    int m = idx / C, c = idx % C;
    float v = w[idx];
    float hi = hfrt(v);
    ht[(size_t)c * M + m] = __float2half(hi);
    lt[(size_t)c * M + m] = __float2half(v - hi);
}

// ---------------------------------------------------------------------------
// fp16 split-MMA GEMM (3 MMAs/product, fp32 acc), 3-stage cp.async pipeline.
// Block 128x128, ktile 32, 128 threads = 4 warps (2x2), 64x64 per warp.
// ---------------------------------------------------------------------------
#define GSTG 34816   // bytes per stage: 4 arrays x 32 x 136 x 2B

template<int M, int K, bool HAS_BIAS, bool SPLIT_OUT>
__global__ __launch_bounds__(128) void gemm_h(
    const __half* __restrict__ Ah_g, const __half* __restrict__ Al_g,
    const __half* __restrict__ Bh_g, const __half* __restrict__ Bl_g,
    const float* __restrict__ bias,
    __half* __restrict__ Yh, __half* __restrict__ Yl,
    float* __restrict__ Yf)
{
    extern __shared__ __align__(16) unsigned char smg[];
    const int NT = K / 32;

    const int b  = blockIdx.z;
    const int m0 = blockIdx.y * 128;
    const int n0 = blockIdx.x * 128;

    const int tid  = threadIdx.x;
    const int lane = tid & 31;
    const int warp = tid >> 5;      // 0..3
    const int wm   = warp >> 1;     // m offset wm*64
    const int wn   = warp & 1;      // n offset wn*64

    unsigned sb = (unsigned)__cvta_generic_to_shared(smg);

    const unsigned offA = ((((lane >> 4) & 1) * 8 + (lane & 7)) * 272)
                        + (wm * 64 + ((lane >> 3) & 1) * 8) * 2;
    const unsigned offB = ((((lane >> 3) & 1) * 8 + (lane & 7)) * 272)
                        + (wn * 64 + ((lane >> 4) & 1) * 8) * 2;

    float acc[4][8][4];
    #pragma unroll
    for (int i = 0; i < 4; i++)
        #pragma unroll
        for (int j = 0; j < 8; j++)
            #pragma unroll
            for (int t = 0; t < 4; t++) acc[i][j][t] = 0.0f;

    auto issue = [&](int kt, int st) {
        unsigned base = sb + st * GSTG;
        int k0 = kt * 32;
        #pragma unroll
        for (int p = 0; p < 4; p++) {
            int q   = tid + p * 128;
            int row = q >> 4;
            int c8  = (q & 15) * 8;
            size_t ga = (size_t)(k0 + row) * M + m0 + c8;
            size_t gb = ((size_t)b * K + k0 + row) * NL + n0 + c8;
            unsigned so = row * 272 + c8 * 2;
            cpa16(base + so,          Ah_g + ga);
            cpa16(base + 8704 + so,   Al_g + ga);
            cpa16(base + 17408 + so,  Bh_g + gb);
            cpa16(base + 26112 + so,  Bl_g + gb);
        }
    };

    issue(0, 0); CPCOMMIT();
    issue(1, 1); CPCOMMIT();

    for (int kt = 0; kt < NT; kt++) {
        CPWAIT(1);
        __syncthreads();
        if (kt + 2 < NT) issue(kt + 2, (kt + 2) % 3);
        CPCOMMIT();

        unsigned base = sb + (kt % 3) * GSTG;
        const unsigned SAH = base, SAL = base + 8704,
                       SBH = base + 17408, SBL = base + 26112;

        #pragma unroll
        for (int kc = 0; kc < 2; kc++) {
            unsigned kb = kc * 16 * 272;
            unsigned bh[4][4], bl[4][4];
            #pragma unroll
            for (int ng = 0; ng < 4; ng++) {
                LDSMX4T(bh[ng][0], bh[ng][1], bh[ng][2], bh[ng][3],
                        SBH + offB + kb + ng * 32);
                LDSMX4T(bl[ng][0], bl[ng][1], bl[ng][2], bl[ng][3],
                        SBL + offB + kb + ng * 32);
            }
            #pragma unroll
            for (int mf = 0; mf < 4; mf++) {
                unsigned ah0,ah1,ah2,ah3, al0,al1,al2,al3;
                LDSMX4T(ah0,ah1,ah2,ah3, SAH + offA + kb + mf * 32);
                LDSMX4T(al0,al1,al2,al3, SAL + offA + kb + mf * 32);
                // pass 1: hi*hi
                #pragma unroll
                for (int ng = 0; ng < 4; ng++) {
                    MMAH(acc[mf][2*ng],   ah0,ah1,ah2,ah3, bh[ng][0],bh[ng][1]);
                    MMAH(acc[mf][2*ng+1], ah0,ah1,ah2,ah3, bh[ng][2],bh[ng][3]);
                }
                // pass 2: hi*lo
                #pragma unroll
                for (int ng = 0; ng < 4; ng++) {
                    MMAH(acc[mf][2*ng],   ah0,ah1,ah2,ah3, bl[ng][0],bl[ng][1]);
                    MMAH(acc[mf][2*ng+1], ah0,ah1,ah2,ah3, bl[ng][2],bl[ng][3]);
                }
                // pass 3: lo*hi
                #pragma unroll
                for (int ng = 0; ng < 4; ng++) {
                    MMAH(acc[mf][2*ng],   al0,al1,al2,al3, bh[ng][0],bh[ng][1]);
                    MMAH(acc[mf][2*ng+1], al0,al1,al2,al3, bh[ng][2],bh[ng][3]);
                }
            }
        }
    }

    // ---- epilogue ----
    const int r0 = lane >> 2;
    const int cp = (lane & 3) * 2;
    #pragma unroll
    for (int mf = 0; mf < 4; mf++) {
        int ml = m0 + wm * 64 + mf * 16 + r0;
        float bv0 = 0.0f, bv1 = 0.0f;
        if (HAS_BIAS) { bv0 = bias[ml]; bv1 = bias[ml + 8]; }
        #pragma unroll
        for (int g = 0; g < 8; g++) {
            int n = n0 + wn * 64 + (g >> 1) * 16 + (g & 1) * 8 + cp;
            float* c = acc[mf][g];
            size_t a0 = ((size_t)b * M + ml) * NL + n;
            size_t a1 = a0 + (size_t)8 * NL;
            if (SPLIT_OUT) {
                *(unsigned*)(Yh + a0) = pckhf(c[0], c[1]);
                *(unsigned*)(Yl + a0) = pckhf(c[0] - hfrt(c[0]), c[1] - hfrt(c[1]));
                *(unsigned*)(Yh + a1) = pckhf(c[2], c[3]);
                *(unsigned*)(Yl + a1) = pckhf(c[2] - hfrt(c[2]), c[3] - hfrt(c[3]));
            } else {
                *(float2*)(Yf + a0) = make_float2(c[0] + bv0, c[1] + bv0);
                *(float2*)(Yf + a1) = make_float2(c[2] + bv1, c[3] + bv1);
            }
        }
    }
}

// ---------------------------------------------------------------------------
// Flash attention, 2-MMA split: S = qh*(kh+kl), O += ph*(vh+vl).
// BM=128 queries, 4 warps x m32 rows, BN=64 keys, 2-stage cp.async K/V.
// smem: QH 17408 + 2 stages x 36864 = 91136 B.
// ---------------------------------------------------------------------------
#define ASTG 36864

__global__ __launch_bounds__(128) void attn_kernel(
    const __half* __restrict__ qkvh, const __half* __restrict__ qkvl,
    __half* __restrict__ atth, __half* __restrict__ attl)
{
    extern __shared__ __align__(16) unsigned char sma[];

    const int tid  = threadIdx.x;
    const int lane = tid & 31;
    const int warp = tid >> 5;
    const int i0 = blockIdx.x * 128;
    const int h  = blockIdx.y;
    const int b  = blockIdx.z;

    const size_t base = ((size_t)b * NOQKV + h * ND) * NL;
    const __half* qph = qkvh + base;
    const __half* kph = qph + (size_t)NHID * NL;
    const __half* kpl = qkvl + base + (size_t)NHID * NL;
    const __half* vph = qph + (size_t)2 * NHID * NL;
    const __half* vpl = qkvl + base + (size_t)2 * NHID * NL;

    unsigned sb = (unsigned)__cvta_generic_to_shared(sma);
    const unsigned QH = sb, KV0 = sb + 17408;

    const unsigned offQ = (((lane >> 4) & 1) * 8 + (lane & 7)) * 272
                        + (warp * 32 + ((lane >> 3) & 1) * 8) * 2;
    const unsigned offK = (((lane >> 3) & 1) * 8 + (lane & 7)) * 144
                        + (((lane >> 4) & 1) * 8) * 2;
    const unsigned offV = (((lane >> 4) & 1) * 8 + (lane & 7)) * 144
                        + (((lane >> 3) & 1) * 8) * 2;

    const float SC = 0.125f * 1.44269504f;

    auto issueKV = [&](int j0, int st) {
        unsigned kb = KV0 + st * ASTG;
        #pragma unroll
        for (int p = 0; p < 4; p++) {
            int q   = tid + p * 128;
            int row = q >> 3;
            int col = (q & 7) * 8;
            unsigned so = row * 144 + col * 2;
            size_t g = (size_t)row * NL + j0 + col;
            cpa16(kb + so,          kph + g);
            cpa16(kb + 9216 + so,   kpl + g);
            cpa16(kb + 18432 + so,  vph + g);
            cpa16(kb + 27648 + so,  vpl + g);
        }
    };

    {
        #pragma unroll
        for (int p = 0; p < 8; p++) {
            int q = tid + p * 128;
            int r = q >> 4, c16 = (q & 15) * 8;
            unsigned so = r * 272 + c16 * 2;
            cpa16(QH + so, qph + (size_t)r * NL + i0 + c16);
        }
        issueKV(0, 0);
        CPCOMMIT();
    }

    float o[2][8][4];
    float mm[2][2], ll[2][2];
    #pragma unroll
    for (int mb = 0; mb < 2; mb++) {
        mm[mb][0] = -1e30f; mm[mb][1] = -1e30f;
        ll[mb][0] = 0.0f;   ll[mb][1] = 0.0f;
        #pragma unroll
        for (int t = 0; t < 8; t++)
            #pragma unroll
            for (int c = 0; c < 4; c++) o[mb][t][c] = 0.0f;
    }

    for (int jt = 0; jt < 32; jt++) {
        if (jt + 1 < 32) issueKV((jt + 1) * 64, (jt + 1) & 1);
        CPCOMMIT();
        if (jt == 31) { CPWAIT(0); } else { CPWAIT(1); }
        __syncthreads();

        unsigned kb = KV0 + (jt & 1) * ASTG;
        const unsigned KH = kb, KL = kb + 9216, VH = kb + 18432, VL = kb + 27648;

        // ---- S = qh*(kh + kl) : 2-pass ----
        float s[2][8][4];
        #pragma unroll
        for (int mb = 0; mb < 2; mb++)
            #pragma unroll
            for (int t = 0; t < 8; t++)
                #pragma unroll
                for (int c = 0; c < 4; c++) s[mb][t][c] = 0.0f;

        #pragma unroll
        for (int kc = 0; kc < 4; kc++) {
            unsigned kcq = kc * 16 * 272;
            unsigned kck = kc * 16 * 144;
            unsigned qa[2][4];
            LDSMX4T(qa[0][0],qa[0][1],qa[0][2],qa[0][3], QH + offQ + kcq);
            LDSMX4T(qa[1][0],qa[1][1],qa[1][2],qa[1][3], QH + offQ + kcq + 32);
            #pragma unroll
            for (int p = 0; p < 4; p++) {
                unsigned nb = p * 32;
                unsigned h0,h1,h2,h3, e0,e1,e2,e3;
                LDSMX4T(h0,h1,h2,h3, KH + offK + kck + nb);
                LDSMX4T(e0,e1,e2,e3, KL + offK + kck + nb);
                #pragma unroll
                for (int mb = 0; mb < 2; mb++) {
                    MMAH(s[mb][2*p],   qa[mb][0],qa[mb][1],qa[mb][2],qa[mb][3], h0,h1);
                    MMAH(s[mb][2*p+1], qa[mb][0],qa[mb][1],qa[mb][2],qa[mb][3], h2,h3);
                }
                #pragma unroll
                for (int mb = 0; mb < 2; mb++) {
                    MMAH(s[mb][2*p],   qa[mb][0],qa[mb][1],qa[mb][2],qa[mb][3], e0,e1);
                    MMAH(s[mb][2*p+1], qa[mb][0],qa[mb][1],qa[mb][2],qa[mb][3], e2,e3);
                }
            }
        }

        // ---- online softmax + P hi fragments ----
        unsigned pah[2][4][4];
        #pragma unroll
        for (int mb = 0; mb < 2; mb++) {
            float mx0 = -1e30f, mx1 = -1e30f;
            #pragma unroll
            for (int t = 0; t < 8; t++) {
                s[mb][t][0] *= SC; s[mb][t][1] *= SC;
                s[mb][t][2] *= SC; s[mb][t][3] *= SC;
                mx0 = fmaxf(mx0, fmaxf(s[mb][t][0], s[mb][t][1]));
                mx1 = fmaxf(mx1, fmaxf(s[mb][t][2], s[mb][t][3]));
            }
            mx0 = fmaxf(mx0, __shfl_xor_sync(0xffffffffu, mx0, 1));
            mx0 = fmaxf(mx0, __shfl_xor_sync(0xffffffffu, mx0, 2));
            mx1 = fmaxf(mx1, __shfl_xor_sync(0xffffffffu, mx1, 1));
            mx1 = fmaxf(mx1, __shfl_xor_sync(0xffffffffu, mx1, 2));
            float mn0 = fmaxf(mm[mb][0], mx0), mn1 = fmaxf(mm[mb][1], mx1);
            float c0 = ex2(mm[mb][0] - mn0),   c1 = ex2(mm[mb][1] - mn1);
            mm[mb][0] = mn0; mm[mb][1] = mn1;

            float rs0 = 0.0f, rs1 = 0.0f;
            #pragma unroll
            for (int t = 0; t < 8; t++) {
                s[mb][t][0] = ex2(s[mb][t][0] - mn0);
                s[mb][t][1] = ex2(s[mb][t][1] - mn0);
                s[mb][t][2] = ex2(s[mb][t][2] - mn1);
                s[mb][t][3] = ex2(s[mb][t][3] - mn1);
                rs0 += s[mb][t][0] + s[mb][t][1];
                rs1 += s[mb][t][2] + s[mb][t][3];
            }
            ll[mb][0] = ll[mb][0] * c0 + rs0;
            ll[mb][1] = ll[mb][1] * c1 + rs1;
            #pragma unroll
            for (int t = 0; t < 8; t++) {
                o[mb][t][0] *= c0; o[mb][t][1] *= c0;
                o[mb][t][2] *= c1; o[mb][t][3] *= c1;
            }
            #pragma unroll
            for (int c = 0; c < 4; c++) {
                int A = 2 * c, B = 2 * c + 1;
                pah[mb][c][0] = pckhf(s[mb][A][0], s[mb][A][1]);
                pah[mb][c][1] = pckhf(s[mb][A][2], s[mb][A][3]);
                pah[mb][c][2] = pckhf(s[mb][B][0], s[mb][B][1]);
                pah[mb][c][3] = pckhf(s[mb][B][2], s[mb][B][3]);
            }
        }

        // ---- O += ph*(vh + vl) : 2-pass ----
        #pragma unroll
        for (int c = 0; c < 4; c++) {
            unsigned jb = c * 32;
            #pragma unroll
            for (int p = 0; p < 4; p++) {
                unsigned db = p * 2304;
                unsigned h0,h1,h2,h3, e0,e1,e2,e3;
                LDSMX4(h0,h1,h2,h3, VH + offV + db + jb);
                LDSMX4(e0,e1,e2,e3, VL + offV + db + jb);
                #pragma unroll
                for (int mb = 0; mb < 2; mb++) {
                    MMAH(o[mb][2*p],   pah[mb][c][0],pah[mb][c][1],pah[mb][c][2],pah[mb][c][3], h0,h1);
                    MMAH(o[mb][2*p+1], pah[mb][c][0],pah[mb][c][1],pah[mb][c][2],pah[mb][c][3], h2,h3);
                }
                #pragma unroll
                for (int mb = 0; mb < 2; mb++) {
                    MMAH(o[mb][2*p],   pah[mb][c][0],pah[mb][c][1],pah[mb][c][2],pah[mb][c][3], e0,e1);
                    MMAH(o[mb][2*p+1], pah[mb][c][0],pah[mb][c][1],pah[mb][c][2],pah[mb][c][3], e2,e3);
                }
            }
        }
        __syncthreads();
    }

    // ---- finalize: write att split [ch][l] ----
    const size_t ob = ((size_t)b * NHID + h * ND) * NL;
    #pragma unroll
    for (int mb = 0; mb < 2; mb++) {
        float l0 = ll[mb][0], l1 = ll[mb][1];
        l0 += __shfl_xor_sync(0xffffffffu, l0, 1);
        l0 += __shfl_xor_sync(0xffffffffu, l0, 2);
        l1 += __shfl_xor_sync(0xffffffffu, l1, 1);
        l1 += __shfl_xor_sync(0xffffffffu, l1, 2);
        float inv0 = __fdividef(1.0f, l0);
        float inv1 = __fdividef(1.0f, l1);

        int ig = i0 + warp * 32 + mb * 16 + (lane >> 2);
        #pragma unroll
        for (int dt = 0; dt < 8; dt++) {
            int d = dt * 8 + (lane & 3) * 2;
            float v0 = o[mb][dt][0] * inv0, v1 = o[mb][dt][1] * inv0;
            float v2 = o[mb][dt][2] * inv1, v3 = o[mb][dt][3] * inv1;
            size_t a0 = ob + (size_t)d * NL + ig;
            size_t a1 = ob + (size_t)(d + 1) * NL + ig;
            atth[a0]     = __float2half(v0);
            attl[a0]     = __float2half(v0 - hfrt(v0));
            atth[a1]     = __float2half(v1);
            attl[a1]     = __float2half(v1 - hfrt(v1));
            atth[a0 + 8] = __float2half(v2);
            attl[a0 + 8] = __float2half(v2 - hfrt(v2));
            atth[a1 + 8] = __float2half(v3);
            attl[a1 + 8] = __float2half(v3 - hfrt(v3));
        }
    }
}

// ---------------------------------------------------------------------------
extern "C" void kernel_launch(void* const* d_in, const int* in_sizes, int n_in,
                              void* d_out, int out_size)
{
    const float* x     = (const float*)d_in[0];
    const float* w_qkv = (const float*)d_in[1];
    const float* w_out = (const float*)d_in[2];
    const float* b_out = (const float*)d_in[3];
    float* out = (float*)d_out;

    __half *xh, *xl, *wqh, *wql, *woh, *wol, *qkvh, *qkvl, *atth, *attl;
    cudaGetSymbolAddress((void**)&xh,   g_xh);
    cudaGetSymbolAddress((void**)&xl,   g_xl);
    cudaGetSymbolAddress((void**)&wqh,  g_wqh);
    cudaGetSymbolAddress((void**)&wql,  g_wql);
    cudaGetSymbolAddress((void**)&woh,  g_woh);
    cudaGetSymbolAddress((void**)&wol,  g_wol);
    cudaGetSymbolAddress((void**)&qkvh, g_qkvh);
    cudaGetSymbolAddress((void**)&qkvl, g_qkvl);
    cudaGetSymbolAddress((void**)&atth, g_atth);
    cudaGetSymbolAddress((void**)&attl, g_attl);

    // 0) split inputs/weights
    cvt_split<<<(NB * NC * NL / 4) / 256, 256>>>(
        (const float4*)x, (uint2*)xh, (uint2*)xl);
    cvt_splitT<<<(NOQKV * NC) / 256, 256>>>(w_qkv, wqh, wql, NOQKV, NC);
    cvt_splitT<<<(NC * NHID) / 256, 256>>>(w_out, woh, wol, NC, NHID);

    const int gsmem = 3 * GSTG;            // 104448
    const int asmem = 17408 + 2 * ASTG;    // 91136

    // 1) QKV projection
    cudaFuncSetAttribute(gemm_h<NOQKV, NC, false, true>,
                         cudaFuncAttributeMaxDynamicSharedMemorySize, gsmem);
    gemm_h<NOQKV, NC, false, true>
        <<<dim3(NL / 128, NOQKV / 128, NB), 128, gsmem>>>(
            wqh, wql, xh, xl, nullptr, qkvh, qkvl, nullptr);

    // 2) Attention
    cudaFuncSetAttribute(attn_kernel,
                         cudaFuncAttributeMaxDynamicSharedMemorySize, asmem);
    attn_kernel<<<dim3(NL / 128, NH, NB), 128, asmem>>>(qkvh, qkvl, atth, attl);

    // 3) Output projection + bias
    cudaFuncSetAttribute(gemm_h<NC, NHID, true, false>,
                         cudaFuncAttributeMaxDynamicSharedMemorySize, gsmem);
    gemm_h<NC, NHID, true, false>
        <<<dim3(NL / 128, NC / 128, NB), 128, gsmem>>>(
            woh, wol, atth, attl, b_out, nullptr, nullptr, out);
}

// round 14
// speedup vs baseline: 1.5062x; 1.2572x over previous
#include <cuda_runtime.h>
#include <cuda_fp16.h>
#include <cstdint>

#define NB    8
#define NC    512
#define NL    2048
#define NH    8
#define ND    64
#define NHID  512
#define NOQKV 1536

// ---------------- device-global scratch (allocation-free) ----------------
__device__ __half g_xh[(size_t)NB * NC * NL];
__device__ __half g_xl[(size_t)NB * NC * NL];
__device__ __half g_wqh[(size_t)NC * NOQKV];    // [c][m] transposed
__device__ __half g_woh[(size_t)NHID * NC];     // [c][m] transposed
__device__ __half g_qkvh[(size_t)NB * NOQKV * NL];
__device__ __half g_qkvl[(size_t)NB * NOQKV * NL];
__device__ __half g_atth[(size_t)NB * NHID * NL];
__device__ __half g_attl[(size_t)NB * NHID * NL];

__device__ __forceinline__ float ex2(float x) {
    float y; asm("ex2.approx.f32 %0, %1;" : "=f"(y) : "f"(x)); return y;
}
// pack two fp32 -> f16x2 {low half = first arg}
__device__ __forceinline__ unsigned pckhf(float lo, float hi) {
    unsigned r; asm("cvt.rn.f16x2.f32 %0, %1, %2;" : "=r"(r) : "f"(hi), "f"(lo)); return r;
}
// fp32 -> fp16 -> fp32 round trip
__device__ __forceinline__ float hfrt(float x) {
    float r;
    asm("{.reg .b16 t; cvt.rn.f16.f32 t, %1; cvt.f32.f16 %0, t;}" : "=f"(r) : "f"(x));
    return r;
}
__device__ __forceinline__ void cpa16(unsigned s, const void* g) {
    asm volatile("cp.async.cg.shared.global [%0], [%1], 16;" :: "r"(s), "l"(g));
}
#define CPCOMMIT() asm volatile("cp.async.commit_group;")
#define CPWAIT(n)  asm volatile("cp.async.wait_group %0;" :: "n"(n))

#define LDSMX4(R0,R1,R2,R3,A) \
    asm volatile("ldmatrix.sync.aligned.m8n8.x4.shared.b16 {%0,%1,%2,%3}, [%4];" \
        : "=r"(R0),"=r"(R1),"=r"(R2),"=r"(R3) : "r"(A))
#define LDSMX4T(R0,R1,R2,R3,A) \
    asm volatile("ldmatrix.sync.aligned.m8n8.x4.trans.shared.b16 {%0,%1,%2,%3}, [%4];" \
        : "=r"(R0),"=r"(R1),"=r"(R2),"=r"(R3) : "r"(A))
// fp16 inputs, fp32 accumulate
#define MMAH(C,A0,A1,A2,A3,B0,B1) \
    asm("mma.sync.aligned.m16n8k16.row.col.f32.f16.f16.f32 " \
        "{%0,%1,%2,%3},{%4,%5,%6,%7},{%8,%9},{%0,%1,%2,%3};" \
        : "+f"((C)[0]),"+f"((C)[1]),"+f"((C)[2]),"+f"((C)[3]) \
        : "r"(A0),"r"(A1),"r"(A2),"r"(A3),"r"(B0),"r"(B1))

// ---------------------------------------------------------------------------
// fp32 -> fp16 hi/lo split passes
// ---------------------------------------------------------------------------
__global__ void cvt_split(const float4* __restrict__ src,
                          uint2* __restrict__ h, uint2* __restrict__ l)
{
    int i = blockIdx.x * blockDim.x + threadIdx.x;
    float4 f = src[i];
    uint2 hv, lv;
    hv.x = pckhf(f.x, f.y);
    hv.y = pckhf(f.z, f.w);
    lv.x = pckhf(f.x - hfrt(f.x), f.y - hfrt(f.y));
    lv.y = pckhf(f.z - hfrt(f.z), f.w - hfrt(f.w));
    h[i] = hv; l[i] = lv;
}

// weights: fp32 [m][c] -> transposed fp16 hi only [c][m] (residue dropped)
__global__ void cvt_hT(const float* __restrict__ w,
                       __half* __restrict__ ht, int M, int C)
{
    int idx = blockIdx.x * blockDim.x + threadIdx.x;
    int m = idx / C, c = idx % C;
    ht[(size_t)c * M + m] = __float2half(w[idx]);
}

// ---------------------------------------------------------------------------
// fp16 2-MMA GEMM: Y = Wh * (Xh + Xl), fp32 acc. 3-stage cp.async pipeline.
// Block 128x128, ktile 32, 128 threads = 4 warps (2x2), 64x64 per warp.
// ---------------------------------------------------------------------------
#define GSTG 26112   // bytes per stage: 3 arrays x 32 x 136 x 2B

template<int M, int K, bool HAS_BIAS, bool SPLIT_OUT>
__global__ __launch_bounds__(128) void gemm_h(
    const __half* __restrict__ Ah_g,
    const __half* __restrict__ Bh_g, const __half* __restrict__ Bl_g,
    const float* __restrict__ bias,
    __half* __restrict__ Yh, __half* __restrict__ Yl,
    float* __restrict__ Yf)
{
    extern __shared__ __align__(16) unsigned char smg[];
    const int NT = K / 32;

    const int b  = blockIdx.z;
    const int m0 = blockIdx.y * 128;
    const int n0 = blockIdx.x * 128;

    const int tid  = threadIdx.x;
    const int lane = tid & 31;
    const int warp = tid >> 5;      // 0..3
    const int wm   = warp >> 1;     // m offset wm*64
    const int wn   = warp & 1;      // n offset wn*64

    unsigned sb = (unsigned)__cvta_generic_to_shared(smg);

    const unsigned offA = ((((lane >> 4) & 1) * 8 + (lane & 7)) * 272)
                        + (wm * 64 + ((lane >> 3) & 1) * 8) * 2;
    const unsigned offB = ((((lane >> 3) & 1) * 8 + (lane & 7)) * 272)
                        + (wn * 64 + ((lane >> 4) & 1) * 8) * 2;

    float acc[4][8][4];
    #pragma unroll
    for (int i = 0; i < 4; i++)
        #pragma unroll
        for (int j = 0; j < 8; j++)
            #pragma unroll
            for (int t = 0; t < 4; t++) acc[i][j][t] = 0.0f;

    auto issue = [&](int kt, int st) {
        unsigned base = sb + st * GSTG;
        int k0 = kt * 32;
        #pragma unroll
        for (int p = 0; p < 4; p++) {
            int q   = tid + p * 128;
            int row = q >> 4;
            int c8  = (q & 15) * 8;
            size_t ga = (size_t)(k0 + row) * M + m0 + c8;
            size_t gb = ((size_t)b * K + k0 + row) * NL + n0 + c8;
            unsigned so = row * 272 + c8 * 2;
            cpa16(base + so,          Ah_g + ga);
            cpa16(base + 8704 + so,   Bh_g + gb);
            cpa16(base + 17408 + so,  Bl_g + gb);
        }
    };

    issue(0, 0); CPCOMMIT();
    issue(1, 1); CPCOMMIT();

    for (int kt = 0; kt < NT; kt++) {
        CPWAIT(1);
        __syncthreads();
        if (kt + 2 < NT) issue(kt + 2, (kt + 2) % 3);
        CPCOMMIT();

        unsigned base = sb + (kt % 3) * GSTG;
        const unsigned SAH = base, SBH = base + 8704, SBL = base + 17408;

        #pragma unroll
        for (int kc = 0; kc < 2; kc++) {
            unsigned kb = kc * 16 * 272;
            unsigned bh[4][4], bl[4][4];
            #pragma unroll
            for (int ng = 0; ng < 4; ng++) {
                LDSMX4T(bh[ng][0], bh[ng][1], bh[ng][2], bh[ng][3],
                        SBH + offB + kb + ng * 32);
                LDSMX4T(bl[ng][0], bl[ng][1], bl[ng][2], bl[ng][3],
                        SBL + offB + kb + ng * 32);
            }
            #pragma unroll
            for (int mf = 0; mf < 4; mf++) {
                unsigned ah0,ah1,ah2,ah3;
                LDSMX4T(ah0,ah1,ah2,ah3, SAH + offA + kb + mf * 32);
                // pass 1: ah * bh
                #pragma unroll
                for (int ng = 0; ng < 4; ng++) {
                    MMAH(acc[mf][2*ng],   ah0,ah1,ah2,ah3, bh[ng][0],bh[ng][1]);
                    MMAH(acc[mf][2*ng+1], ah0,ah1,ah2,ah3, bh[ng][2],bh[ng][3]);
                }
                // pass 2: ah * bl
                #pragma unroll
                for (int ng = 0; ng < 4; ng++) {
                    MMAH(acc[mf][2*ng],   ah0,ah1,ah2,ah3, bl[ng][0],bl[ng][1]);
                    MMAH(acc[mf][2*ng+1], ah0,ah1,ah2,ah3, bl[ng][2],bl[ng][3]);
                }
            }
        }
    }

    // ---- epilogue ----
    const int r0 = lane >> 2;
    const int cp = (lane & 3) * 2;
    #pragma unroll
    for (int mf = 0; mf < 4; mf++) {
        int ml = m0 + wm * 64 + mf * 16 + r0;
        float bv0 = 0.0f, bv1 = 0.0f;
        if (HAS_BIAS) { bv0 = bias[ml]; bv1 = bias[ml + 8]; }
        #pragma unroll
        for (int g = 0; g < 8; g++) {
            int n = n0 + wn * 64 + (g >> 1) * 16 + (g & 1) * 8 + cp;
            float* c = acc[mf][g];
            size_t a0 = ((size_t)b * M + ml) * NL + n;
            size_t a1 = a0 + (size_t)8 * NL;
            if (SPLIT_OUT) {
                *(unsigned*)(Yh + a0) = pckhf(c[0], c[1]);
                *(unsigned*)(Yl + a0) = pckhf(c[0] - hfrt(c[0]), c[1] - hfrt(c[1]));
                *(unsigned*)(Yh + a1) = pckhf(c[2], c[3]);
                *(unsigned*)(Yl + a1) = pckhf(c[2] - hfrt(c[2]), c[3] - hfrt(c[3]));
            } else {
                *(float2*)(Yf + a0) = make_float2(c[0] + bv0, c[1] + bv0);
                *(float2*)(Yf + a1) = make_float2(c[2] + bv1, c[3] + bv1);
            }
        }
    }
}

// ---------------------------------------------------------------------------
// Flash attention: S = qh*(kh+kl) [2 MMAs], O += ph*vh [1 MMA].
// BM=128 queries, 4 warps x m32 rows, BN=64 keys, 2-stage cp.async K/V.
// smem: QH 17408 + 2 stages x 27648 = 72704 B.
// ---------------------------------------------------------------------------
#define ASTG 27648

__global__ __launch_bounds__(128) void attn_kernel(
    const __half* __restrict__ qkvh, const __half* __restrict__ qkvl,
    __half* __restrict__ atth, __half* __restrict__ attl)
{
    extern __shared__ __align__(16) unsigned char sma[];

    const int tid  = threadIdx.x;
    const int lane = tid & 31;
    const int warp = tid >> 5;
    const int i0 = blockIdx.x * 128;
    const int h  = blockIdx.y;
    const int b  = blockIdx.z;

    const size_t base = ((size_t)b * NOQKV + h * ND) * NL;
    const __half* qph = qkvh + base;
    const __half* kph = qph + (size_t)NHID * NL;
    const __half* kpl = qkvl + base + (size_t)NHID * NL;
    const __half* vph = qph + (size_t)2 * NHID * NL;

    unsigned sb = (unsigned)__cvta_generic_to_shared(sma);
    const unsigned QH = sb, KV0 = sb + 17408;

    const unsigned offQ = (((lane >> 4) & 1) * 8 + (lane & 7)) * 272
                        + (warp * 32 + ((lane >> 3) & 1) * 8) * 2;
    const unsigned offK = (((lane >> 3) & 1) * 8 + (lane & 7)) * 144
                        + (((lane >> 4) & 1) * 8) * 2;
    const unsigned offV = (((lane >> 4) & 1) * 8 + (lane & 7)) * 144
                        + (((lane >> 3) & 1) * 8) * 2;

    const float SC = 0.125f * 1.44269504f;

    auto issueKV = [&](int j0, int st) {
        unsigned kb = KV0 + st * ASTG;
        #pragma unroll
        for (int p = 0; p < 4; p++) {
            int q   = tid + p * 128;
            int row = q >> 3;
            int col = (q & 7) * 8;
            unsigned so = row * 144 + col * 2;
            size_t g = (size_t)row * NL + j0 + col;
            cpa16(kb + so,          kph + g);
            cpa16(kb + 9216 + so,   kpl + g);
            cpa16(kb + 18432 + so,  vph + g);
        }
    };

    {
        #pragma unroll
        for (int p = 0; p < 8; p++) {
            int q = tid + p * 128;
            int r = q >> 4, c16 = (q & 15) * 8;
            unsigned so = r * 272 + c16 * 2;
            cpa16(QH + so, qph + (size_t)r * NL + i0 + c16);
        }
        issueKV(0, 0);
        CPCOMMIT();
    }

    float o[2][8][4];
    float mm[2][2], ll[2][2];
    #pragma unroll
    for (int mb = 0; mb < 2; mb++) {
        mm[mb][0] = -1e30f; mm[mb][1] = -1e30f;
        ll[mb][0] = 0.0f;   ll[mb][1] = 0.0f;
        #pragma unroll
        for (int t = 0; t < 8; t++)
            #pragma unroll
            for (int c = 0; c < 4; c++) o[mb][t][c] = 0.0f;
    }

    for (int jt = 0; jt < 32; jt++) {
        if (jt + 1 < 32) issueKV((jt + 1) * 64, (jt + 1) & 1);
        CPCOMMIT();
        if (jt == 31) { CPWAIT(0); } else { CPWAIT(1); }
        __syncthreads();

        unsigned kb = KV0 + (jt & 1) * ASTG;
        const unsigned KH = kb, KL = kb + 9216, VH = kb + 18432;

        // ---- S = qh*(kh + kl) : 2-pass ----
        float s[2][8][4];
        #pragma unroll
        for (int mb = 0; mb < 2; mb++)
            #pragma unroll
            for (int t = 0; t < 8; t++)
                #pragma unroll
                for (int c = 0; c < 4; c++) s[mb][t][c] = 0.0f;

        #pragma unroll
        for (int kc = 0; kc < 4; kc++) {
            unsigned kcq = kc * 16 * 272;
            unsigned kck = kc * 16 * 144;
            unsigned qa[2][4];
            LDSMX4T(qa[0][0],qa[0][1],qa[0][2],qa[0][3], QH + offQ + kcq);
            LDSMX4T(qa[1][0],qa[1][1],qa[1][2],qa[1][3], QH + offQ + kcq + 32);
            #pragma unroll
            for (int p = 0; p < 4; p++) {
                unsigned nb = p * 32;
                unsigned h0,h1,h2,h3, e0,e1,e2,e3;
                LDSMX4T(h0,h1,h2,h3, KH + offK + kck + nb);
                LDSMX4T(e0,e1,e2,e3, KL + offK + kck + nb);
                #pragma unroll
                for (int mb = 0; mb < 2; mb++) {
                    MMAH(s[mb][2*p],   qa[mb][0],qa[mb][1],qa[mb][2],qa[mb][3], h0,h1);
                    MMAH(s[mb][2*p+1], qa[mb][0],qa[mb][1],qa[mb][2],qa[mb][3], h2,h3);
                }
                #pragma unroll
                for (int mb = 0; mb < 2; mb++) {
                    MMAH(s[mb][2*p],   qa[mb][0],qa[mb][1],qa[mb][2],qa[mb][3], e0,e1);
                    MMAH(s[mb][2*p+1], qa[mb][0],qa[mb][1],qa[mb][2],qa[mb][3], e2,e3);
                }
            }
        }

        // ---- online softmax + P hi fragments ----
        unsigned pah[2][4][4];
        #pragma unroll
        for (int mb = 0; mb < 2; mb++) {
            float mx0 = -1e30f, mx1 = -1e30f;
            #pragma unroll
            for (int t = 0; t < 8; t++) {
                s[mb][t][0] *= SC; s[mb][t][1] *= SC;
                s[mb][t][2] *= SC; s[mb][t][3] *= SC;
                mx0 = fmaxf(mx0, fmaxf(s[mb][t][0], s[mb][t][1]));
                mx1 = fmaxf(mx1, fmaxf(s[mb][t][2], s[mb][t][3]));
            }
            mx0 = fmaxf(mx0, __shfl_xor_sync(0xffffffffu, mx0, 1));
            mx0 = fmaxf(mx0, __shfl_xor_sync(0xffffffffu, mx0, 2));
            mx1 = fmaxf(mx1, __shfl_xor_sync(0xffffffffu, mx1, 1));
            mx1 = fmaxf(mx1, __shfl_xor_sync(0xffffffffu, mx1, 2));
            float mn0 = fmaxf(mm[mb][0], mx0), mn1 = fmaxf(mm[mb][1], mx1);
            float c0 = ex2(mm[mb][0] - mn0),   c1 = ex2(mm[mb][1] - mn1);
            mm[mb][0] = mn0; mm[mb][1] = mn1;

            float rs0 = 0.0f, rs1 = 0.0f;
            #pragma unroll
            for (int t = 0; t < 8; t++) {
                s[mb][t][0] = ex2(s[mb][t][0] - mn0);
                s[mb][t][1] = ex2(s[mb][t][1] - mn0);
                s[mb][t][2] = ex2(s[mb][t][2] - mn1);
                s[mb][t][3] = ex2(s[mb][t][3] - mn1);
                rs0 += s[mb][t][0] + s[mb][t][1];
                rs1 += s[mb][t][2] + s[mb][t][3];
            }
            ll[mb][0] = ll[mb][0] * c0 + rs0;
            ll[mb][1] = ll[mb][1] * c1 + rs1;
            #pragma unroll
            for (int t = 0; t < 8; t++) {
                o[mb][t][0] *= c0; o[mb][t][1] *= c0;
                o[mb][t][2] *= c1; o[mb][t][3] *= c1;
            }
            #pragma unroll
            for (int c = 0; c < 4; c++) {
                int A = 2 * c, B = 2 * c + 1;
                pah[mb][c][0] = pckhf(s[mb][A][0], s[mb][A][1]);
                pah[mb][c][1] = pckhf(s[mb][A][2], s[mb][A][3]);
                pah[mb][c][2] = pckhf(s[mb][B][0], s[mb][B][1]);
                pah[mb][c][3] = pckhf(s[mb][B][2], s[mb][B][3]);
            }
        }

        // ---- O += ph * vh : 1-pass ----
        #pragma unroll
        for (int c = 0; c < 4; c++) {
            unsigned jb = c * 32;
            #pragma unroll
            for (int p = 0; p < 4; p++) {
                unsigned db = p * 2304;
                unsigned h0,h1,h2,h3;
                LDSMX4(h0,h1,h2,h3, VH + offV + db + jb);
                #pragma unroll
                for (int mb = 0; mb < 2; mb++) {
                    MMAH(o[mb][2*p],   pah[mb][c][0],pah[mb][c][1],pah[mb][c][2],pah[mb][c][3], h0,h1);
                    MMAH(o[mb][2*p+1], pah[mb][c][0],pah[mb][c][1],pah[mb][c][2],pah[mb][c][3], h2,h3);
                }
            }
        }
        __syncthreads();
    }

    // ---- finalize: write att split [ch][l] ----
    const size_t ob = ((size_t)b * NHID + h * ND) * NL;
    #pragma unroll
    for (int mb = 0; mb < 2; mb++) {
        float l0 = ll[mb][0], l1 = ll[mb][1];
        l0 += __shfl_xor_sync(0xffffffffu, l0, 1);
        l0 += __shfl_xor_sync(0xffffffffu, l0, 2);
        l1 += __shfl_xor_sync(0xffffffffu, l1, 1);
        l1 += __shfl_xor_sync(0xffffffffu, l1, 2);
        float inv0 = __fdividef(1.0f, l0);
        float inv1 = __fdividef(1.0f, l1);

        int ig = i0 + warp * 32 + mb * 16 + (lane >> 2);
        #pragma unroll
        for (int dt = 0; dt < 8; dt++) {
            int d = dt * 8 + (lane & 3) * 2;
            float v0 = o[mb][dt][0] * inv0, v1 = o[mb][dt][1] * inv0;
            float v2 = o[mb][dt][2] * inv1, v3 = o[mb][dt][3] * inv1;
            size_t a0 = ob + (size_t)d * NL + ig;
            size_t a1 = ob + (size_t)(d + 1) * NL + ig;
            atth[a0]     = __float2half(v0);
            attl[a0]     = __float2half(v0 - hfrt(v0));
            atth[a1]     = __float2half(v1);
            attl[a1]     = __float2half(v1 - hfrt(v1));
            atth[a0 + 8] = __float2half(v2);
            attl[a0 + 8] = __float2half(v2 - hfrt(v2));
            atth[a1 + 8] = __float2half(v3);
            attl[a1 + 8] = __float2half(v3 - hfrt(v3));
        }
    }
}

// ---------------------------------------------------------------------------
extern "C" void kernel_launch(void* const* d_in, const int* in_sizes, int n_in,
                              void* d_out, int out_size)
{
    const float* x     = (const float*)d_in[0];
    const float* w_qkv = (const float*)d_in[1];
    const float* w_out = (const float*)d_in[2];
    const float* b_out = (const float*)d_in[3];
    float* out = (float*)d_out;

    __half *xh, *xl, *wqh, *woh, *qkvh, *qkvl, *atth, *attl;
    cudaGetSymbolAddress((void**)&xh,   g_xh);
    cudaGetSymbolAddress((void**)&xl,   g_xl);
    cudaGetSymbolAddress((void**)&wqh,  g_wqh);
    cudaGetSymbolAddress((void**)&woh,  g_woh);
    cudaGetSymbolAddress((void**)&qkvh, g_qkvh);
    cudaGetSymbolAddress((void**)&qkvl, g_qkvl);
    cudaGetSymbolAddress((void**)&atth, g_atth);
    cudaGetSymbolAddress((void**)&attl, g_attl);

    // 0) split x (hi+lo); weights hi-only transposed
    cvt_split<<<(NB * NC * NL / 4) / 256, 256>>>(
        (const float4*)x, (uint2*)xh, (uint2*)xl);
    cvt_hT<<<(NOQKV * NC) / 256, 256>>>(w_qkv, wqh, NOQKV, NC);
    cvt_hT<<<(NC * NHID) / 256, 256>>>(w_out, woh, NC, NHID);

    const int gsmem = 3 * GSTG;            // 78336
    const int asmem = 17408 + 2 * ASTG;    // 72704

    // 1) QKV projection (2-MMA)
    cudaFuncSetAttribute(gemm_h<NOQKV, NC, false, true>,
                         cudaFuncAttributeMaxDynamicSharedMemorySize, gsmem);
    gemm_h<NOQKV, NC, false, true>
        <<<dim3(NL / 128, NOQKV / 128, NB), 128, gsmem>>>(
            wqh, xh, xl, nullptr, qkvh, qkvl, nullptr);

    // 2) Attention (QK 2-MMA, PV 1-MMA)
    cudaFuncSetAttribute(attn_kernel,
                         cudaFuncAttributeMaxDynamicSharedMemorySize, asmem);
    attn_kernel<<<dim3(NL / 128, NH, NB), 128, asmem>>>(qkvh, qkvl, atth, attl);

    // 3) Output projection + bias (2-MMA)
    cudaFuncSetAttribute(gemm_h<NC, NHID, true, false>,
                         cudaFuncAttributeMaxDynamicSharedMemorySize, gsmem);
    gemm_h<NC, NHID, true, false>
        <<<dim3(NL / 128, NC / 128, NB), 128, gsmem>>>(
            woh, atth, attl, b_out, nullptr, nullptr, out);
}

// round 15
// speedup vs baseline: 2.0255x; 1.3447x over previous
#include <cuda_runtime.h>
#include <cuda_fp16.h>
#include <cstdint>

#define NB    8
#define NC    512
#define NL    2048
#define NH    8
#define ND    64
#define NHID  512
#define NOQKV 1536

// ---------------- device-global scratch (allocation-free) ----------------
__device__ __half g_xh[(size_t)NB * NC * NL];
__device__ __half g_xl[(size_t)NB * NC * NL];
__device__ __half g_wqh[(size_t)NC * NOQKV];    // [c][m] transposed
__device__ __half g_woh[(size_t)NHID * NC];     // [c][m] transposed
__device__ __half g_qkvh[(size_t)NB * NOQKV * NL];
__device__ __half g_atth[(size_t)NB * NHID * NL];

__device__ __forceinline__ float ex2(float x) {
    float y; asm("ex2.approx.f32 %0, %1;" : "=f"(y) : "f"(x)); return y;
}
// pack two fp32 -> f16x2 {low half = first arg}
__device__ __forceinline__ unsigned pckhf(float lo, float hi) {
    unsigned r; asm("cvt.rn.f16x2.f32 %0, %1, %2;" : "=r"(r) : "f"(hi), "f"(lo)); return r;
}
// fp32 -> fp16 -> fp32 round trip
__device__ __forceinline__ float hfrt(float x) {
    float r;
    asm("{.reg .b16 t; cvt.rn.f16.f32 t, %1; cvt.f32.f16 %0, t;}" : "=f"(r) : "f"(x));
    return r;
}
__device__ __forceinline__ void cpa16(unsigned s, const void* g) {
    asm volatile("cp.async.cg.shared.global [%0], [%1], 16;" :: "r"(s), "l"(g));
}
#define CPCOMMIT() asm volatile("cp.async.commit_group;")
#define CPWAIT(n)  asm volatile("cp.async.wait_group %0;" :: "n"(n))

#define LDSMX4(R0,R1,R2,R3,A) \
    asm volatile("ldmatrix.sync.aligned.m8n8.x4.shared.b16 {%0,%1,%2,%3}, [%4];" \
        : "=r"(R0),"=r"(R1),"=r"(R2),"=r"(R3) : "r"(A))
#define LDSMX4T(R0,R1,R2,R3,A) \
    asm volatile("ldmatrix.sync.aligned.m8n8.x4.trans.shared.b16 {%0,%1,%2,%3}, [%4];" \
        : "=r"(R0),"=r"(R1),"=r"(R2),"=r"(R3) : "r"(A))
// fp16 inputs, fp32 accumulate
#define MMAH(C,A0,A1,A2,A3,B0,B1) \
    asm("mma.sync.aligned.m16n8k16.row.col.f32.f16.f16.f32 " \
        "{%0,%1,%2,%3},{%4,%5,%6,%7},{%8,%9},{%0,%1,%2,%3};" \
        : "+f"((C)[0]),"+f"((C)[1]),"+f"((C)[2]),"+f"((C)[3]) \
        : "r"(A0),"r"(A1),"r"(A2),"r"(A3),"r"(B0),"r"(B1))

// ---------------------------------------------------------------------------
// fp32 -> fp16 hi/lo split passes
// ---------------------------------------------------------------------------
__global__ void cvt_split(const float4* __restrict__ src,
                          uint2* __restrict__ h, uint2* __restrict__ l)
{
    int i = blockIdx.x * blockDim.x + threadIdx.x;
    float4 f = src[i];
    uint2 hv, lv;
    hv.x = pckhf(f.x, f.y);
    hv.y = pckhf(f.z, f.w);
    lv.x = pckhf(f.x - hfrt(f.x), f.y - hfrt(f.y));
    lv.y = pckhf(f.z - hfrt(f.z), f.w - hfrt(f.w));
    h[i] = hv; l[i] = lv;
}

// weights: fp32 [m][c] -> transposed fp16 hi only [c][m]
__global__ void cvt_hT(const float* __restrict__ w,
                       __half* __restrict__ ht, int M, int C)
{
    int idx = blockIdx.x * blockDim.x + threadIdx.x;
    int m = idx / C, c = idx % C;
    ht[(size_t)c * M + m] = __float2half(w[idx]);
}

// ---------------------------------------------------------------------------
// fp16 GEMM, 3-stage cp.async pipeline, fp32 acc.
// BLO=true : Y = Ah * (Bh + Bl)   (2 MMAs/product)
// BLO=false: Y = Ah * Bh          (1 MMA/product)
// Block 128x128, ktile 32, 128 threads = 4 warps (2x2), 64x64 per warp.
// ---------------------------------------------------------------------------
template<int M, int K, bool HAS_BIAS, bool SPLIT_OUT, bool BLO>
__global__ __launch_bounds__(128) void gemm_h(
    const __half* __restrict__ Ah_g,
    const __half* __restrict__ Bh_g, const __half* __restrict__ Bl_g,
    const float* __restrict__ bias,
    __half* __restrict__ Yh, float* __restrict__ Yf)
{
    constexpr int STG = (BLO ? 3 : 2) * 8704;   // bytes per stage
    extern __shared__ __align__(16) unsigned char smg[];
    const int NT = K / 32;

    const int b  = blockIdx.z;
    const int m0 = blockIdx.y * 128;
    const int n0 = blockIdx.x * 128;

    const int tid  = threadIdx.x;
    const int lane = tid & 31;
    const int warp = tid >> 5;      // 0..3
    const int wm   = warp >> 1;     // m offset wm*64
    const int wn   = warp & 1;      // n offset wn*64

    unsigned sb = (unsigned)__cvta_generic_to_shared(smg);

    const unsigned offA = ((((lane >> 4) & 1) * 8 + (lane & 7)) * 272)
                        + (wm * 64 + ((lane >> 3) & 1) * 8) * 2;
    const unsigned offB = ((((lane >> 3) & 1) * 8 + (lane & 7)) * 272)
                        + (wn * 64 + ((lane >> 4) & 1) * 8) * 2;

    float acc[4][8][4];
    #pragma unroll
    for (int i = 0; i < 4; i++)
        #pragma unroll
        for (int j = 0; j < 8; j++)
            #pragma unroll
            for (int t = 0; t < 4; t++) acc[i][j][t] = 0.0f;

    auto issue = [&](int kt, int st) {
        unsigned base = sb + st * STG;
        int k0 = kt * 32;
        #pragma unroll
        for (int p = 0; p < 4; p++) {
            int q   = tid + p * 128;
            int row = q >> 4;
            int c8  = (q & 15) * 8;
            size_t ga = (size_t)(k0 + row) * M + m0 + c8;
            size_t gb = ((size_t)b * K + k0 + row) * NL + n0 + c8;
            unsigned so = row * 272 + c8 * 2;
            cpa16(base + so,          Ah_g + ga);
            cpa16(base + 8704 + so,   Bh_g + gb);
            if (BLO) cpa16(base + 17408 + so, Bl_g + gb);
        }
    };

    issue(0, 0); CPCOMMIT();
    issue(1, 1); CPCOMMIT();

    for (int kt = 0; kt < NT; kt++) {
        CPWAIT(1);
        __syncthreads();
        if (kt + 2 < NT) issue(kt + 2, (kt + 2) % 3);
        CPCOMMIT();

        unsigned base = sb + (kt % 3) * STG;
        const unsigned SAH = base, SBH = base + 8704, SBL = base + 17408;

        #pragma unroll
        for (int kc = 0; kc < 2; kc++) {
            unsigned kb = kc * 16 * 272;
            unsigned bh[4][4], bl[4][4];
            #pragma unroll
            for (int ng = 0; ng < 4; ng++) {
                LDSMX4T(bh[ng][0], bh[ng][1], bh[ng][2], bh[ng][3],
                        SBH + offB + kb + ng * 32);
                if (BLO)
                    LDSMX4T(bl[ng][0], bl[ng][1], bl[ng][2], bl[ng][3],
                            SBL + offB + kb + ng * 32);
            }
            #pragma unroll
            for (int mf = 0; mf < 4; mf++) {
                unsigned ah0,ah1,ah2,ah3;
                LDSMX4T(ah0,ah1,ah2,ah3, SAH + offA + kb + mf * 32);
                // pass 1: ah * bh
                #pragma unroll
                for (int ng = 0; ng < 4; ng++) {
                    MMAH(acc[mf][2*ng],   ah0,ah1,ah2,ah3, bh[ng][0],bh[ng][1]);
                    MMAH(acc[mf][2*ng+1], ah0,ah1,ah2,ah3, bh[ng][2],bh[ng][3]);
                }
                // pass 2: ah * bl
                if (BLO) {
                    #pragma unroll
                    for (int ng = 0; ng < 4; ng++) {
                        MMAH(acc[mf][2*ng],   ah0,ah1,ah2,ah3, bl[ng][0],bl[ng][1]);
                        MMAH(acc[mf][2*ng+1], ah0,ah1,ah2,ah3, bl[ng][2],bl[ng][3]);
                    }
                }
            }
        }
    }

    // ---- epilogue ----
    const int r0 = lane >> 2;
    const int cp = (lane & 3) * 2;
    #pragma unroll
    for (int mf = 0; mf < 4; mf++) {
        int ml = m0 + wm * 64 + mf * 16 + r0;
        float bv0 = 0.0f, bv1 = 0.0f;
        if (HAS_BIAS) { bv0 = bias[ml]; bv1 = bias[ml + 8]; }
        #pragma unroll
        for (int g = 0; g < 8; g++) {
            int n = n0 + wn * 64 + (g >> 1) * 16 + (g & 1) * 8 + cp;
            float* c = acc[mf][g];
            size_t a0 = ((size_t)b * M + ml) * NL + n;
            size_t a1 = a0 + (size_t)8 * NL;
            if (SPLIT_OUT) {
                *(unsigned*)(Yh + a0) = pckhf(c[0], c[1]);
                *(unsigned*)(Yh + a1) = pckhf(c[2], c[3]);
            } else {
                *(float2*)(Yf + a0) = make_float2(c[0] + bv0, c[1] + bv0);
                *(float2*)(Yf + a1) = make_float2(c[2] + bv1, c[3] + bv1);
            }
        }
    }
}

// ---------------------------------------------------------------------------
// Flash attention, pure-fp16 operands: S = qh*kh [1 MMA], O += ph*vh [1 MMA].
// BM=128 queries, 4 warps x m32 rows, BN=64 keys, 2-stage cp.async K/V.
// smem: QH 17408 + 2 stages x 18432 = 54272 B.
// ---------------------------------------------------------------------------
#define ASTG 18432

__global__ __launch_bounds__(128) void attn_kernel(
    const __half* __restrict__ qkvh, __half* __restrict__ atth)
{
    extern __shared__ __align__(16) unsigned char sma[];

    const int tid  = threadIdx.x;
    const int lane = tid & 31;
    const int warp = tid >> 5;
    const int i0 = blockIdx.x * 128;
    const int h  = blockIdx.y;
    const int b  = blockIdx.z;

    const size_t base = ((size_t)b * NOQKV + h * ND) * NL;
    const __half* qph = qkvh + base;
    const __half* kph = qph + (size_t)NHID * NL;
    const __half* vph = qph + (size_t)2 * NHID * NL;

    unsigned sb = (unsigned)__cvta_generic_to_shared(sma);
    const unsigned QH = sb, KV0 = sb + 17408;

    const unsigned offQ = (((lane >> 4) & 1) * 8 + (lane & 7)) * 272
                        + (warp * 32 + ((lane >> 3) & 1) * 8) * 2;
    const unsigned offK = (((lane >> 3) & 1) * 8 + (lane & 7)) * 144
                        + (((lane >> 4) & 1) * 8) * 2;
    const unsigned offV = (((lane >> 4) & 1) * 8 + (lane & 7)) * 144
                        + (((lane >> 3) & 1) * 8) * 2;

    const float SC = 0.125f * 1.44269504f;

    auto issueKV = [&](int j0, int st) {
        unsigned kb = KV0 + st * ASTG;
        #pragma unroll
        for (int p = 0; p < 4; p++) {
            int q   = tid + p * 128;
            int row = q >> 3;
            int col = (q & 7) * 8;
            unsigned so = row * 144 + col * 2;
            size_t g = (size_t)row * NL + j0 + col;
            cpa16(kb + so,          kph + g);
            cpa16(kb + 9216 + so,   vph + g);
        }
    };

    {
        #pragma unroll
        for (int p = 0; p < 8; p++) {
            int q = tid + p * 128;
            int r = q >> 4, c16 = (q & 15) * 8;
            unsigned so = r * 272 + c16 * 2;
            cpa16(QH + so, qph + (size_t)r * NL + i0 + c16);
        }
        issueKV(0, 0);
        CPCOMMIT();
    }

    float o[2][8][4];
    float mm[2][2], ll[2][2];
    #pragma unroll
    for (int mb = 0; mb < 2; mb++) {
        mm[mb][0] = -1e30f; mm[mb][1] = -1e30f;
        ll[mb][0] = 0.0f;   ll[mb][1] = 0.0f;
        #pragma unroll
        for (int t = 0; t < 8; t++)
            #pragma unroll
            for (int c = 0; c < 4; c++) o[mb][t][c] = 0.0f;
    }

    for (int jt = 0; jt < 32; jt++) {
        if (jt + 1 < 32) issueKV((jt + 1) * 64, (jt + 1) & 1);
        CPCOMMIT();
        if (jt == 31) { CPWAIT(0); } else { CPWAIT(1); }
        __syncthreads();

        unsigned kb = KV0 + (jt & 1) * ASTG;
        const unsigned KH = kb, VH = kb + 9216;

        // ---- S = qh * kh : 1-pass ----
        float s[2][8][4];
        #pragma unroll
        for (int mb = 0; mb < 2; mb++)
            #pragma unroll
            for (int t = 0; t < 8; t++)
                #pragma unroll
                for (int c = 0; c < 4; c++) s[mb][t][c] = 0.0f;

        #pragma unroll
        for (int kc = 0; kc < 4; kc++) {
            unsigned kcq = kc * 16 * 272;
            unsigned kck = kc * 16 * 144;
            unsigned qa[2][4];
            LDSMX4T(qa[0][0],qa[0][1],qa[0][2],qa[0][3], QH + offQ + kcq);
            LDSMX4T(qa[1][0],qa[1][1],qa[1][2],qa[1][3], QH + offQ + kcq + 32);
            #pragma unroll
            for (int p = 0; p < 4; p++) {
                unsigned nb = p * 32;
                unsigned h0,h1,h2,h3;
                LDSMX4T(h0,h1,h2,h3, KH + offK + kck + nb);
                #pragma unroll
                for (int mb = 0; mb < 2; mb++) {
                    MMAH(s[mb][2*p],   qa[mb][0],qa[mb][1],qa[mb][2],qa[mb][3], h0,h1);
                    MMAH(s[mb][2*p+1], qa[mb][0],qa[mb][1],qa[mb][2],qa[mb][3], h2,h3);
                }
            }
        }

        // ---- online softmax + P hi fragments ----
        unsigned pah[2][4][4];
        #pragma unroll
        for (int mb = 0; mb < 2; mb++) {
            float mx0 = -1e30f, mx1 = -1e30f;
            #pragma unroll
            for (int t = 0; t < 8; t++) {
                s[mb][t][0] *= SC; s[mb][t][1] *= SC;
                s[mb][t][2] *= SC; s[mb][t][3] *= SC;
                mx0 = fmaxf(mx0, fmaxf(s[mb][t][0], s[mb][t][1]));
                mx1 = fmaxf(mx1, fmaxf(s[mb][t][2], s[mb][t][3]));
            }
            mx0 = fmaxf(mx0, __shfl_xor_sync(0xffffffffu, mx0, 1));
            mx0 = fmaxf(mx0, __shfl_xor_sync(0xffffffffu, mx0, 2));
            mx1 = fmaxf(mx1, __shfl_xor_sync(0xffffffffu, mx1, 1));
            mx1 = fmaxf(mx1, __shfl_xor_sync(0xffffffffu, mx1, 2));
            float mn0 = fmaxf(mm[mb][0], mx0), mn1 = fmaxf(mm[mb][1], mx1);
            float c0 = ex2(mm[mb][0] - mn0),   c1 = ex2(mm[mb][1] - mn1);
            mm[mb][0] = mn0; mm[mb][1] = mn1;

            float rs0 = 0.0f, rs1 = 0.0f;
            #pragma unroll
            for (int t = 0; t < 8; t++) {
                s[mb][t][0] = ex2(s[mb][t][0] - mn0);
                s[mb][t][1] = ex2(s[mb][t][1] - mn0);
                s[mb][t][2] = ex2(s[mb][t][2] - mn1);
                s[mb][t][3] = ex2(s[mb][t][3] - mn1);
                rs0 += s[mb][t][0] + s[mb][t][1];
                rs1 += s[mb][t][2] + s[mb][t][3];
            }
            ll[mb][0] = ll[mb][0] * c0 + rs0;
            ll[mb][1] = ll[mb][1] * c1 + rs1;
            #pragma unroll
            for (int t = 0; t < 8; t++) {
                o[mb][t][0] *= c0; o[mb][t][1] *= c0;
                o[mb][t][2] *= c1; o[mb][t][3] *= c1;
            }
            #pragma unroll
            for (int c = 0; c < 4; c++) {
                int A = 2 * c, B = 2 * c + 1;
                pah[mb][c][0] = pckhf(s[mb][A][0], s[mb][A][1]);
                pah[mb][c][1] = pckhf(s[mb][A][2], s[mb][A][3]);
                pah[mb][c][2] = pckhf(s[mb][B][0], s[mb][B][1]);
                pah[mb][c][3] = pckhf(s[mb][B][2], s[mb][B][3]);
            }
        }

        // ---- O += ph * vh : 1-pass ----
        #pragma unroll
        for (int c = 0; c < 4; c++) {
            unsigned jb = c * 32;
            #pragma unroll
            for (int p = 0; p < 4; p++) {
                unsigned db = p * 2304;
                unsigned h0,h1,h2,h3;
                LDSMX4(h0,h1,h2,h3, VH + offV + db + jb);
                #pragma unroll
                for (int mb = 0; mb < 2; mb++) {
                    MMAH(o[mb][2*p],   pah[mb][c][0],pah[mb][c][1],pah[mb][c][2],pah[mb][c][3], h0,h1);
                    MMAH(o[mb][2*p+1], pah[mb][c][0],pah[mb][c][1],pah[mb][c][2],pah[mb][c][3], h2,h3);
                }
            }
        }
        __syncthreads();
    }

    // ---- finalize: write att hi [ch][l] ----
    const size_t ob = ((size_t)b * NHID + h * ND) * NL;
    #pragma unroll
    for (int mb = 0; mb < 2; mb++) {
        float l0 = ll[mb][0], l1 = ll[mb][1];
        l0 += __shfl_xor_sync(0xffffffffu, l0, 1);
        l0 += __shfl_xor_sync(0xffffffffu, l0, 2);
        l1 += __shfl_xor_sync(0xffffffffu, l1, 1);
        l1 += __shfl_xor_sync(0xffffffffu, l1, 2);
        float inv0 = __fdividef(1.0f, l0);
        float inv1 = __fdividef(1.0f, l1);

        int ig = i0 + warp * 32 + mb * 16 + (lane >> 2);
        #pragma unroll
        for (int dt = 0; dt < 8; dt++) {
            int d = dt * 8 + (lane & 3) * 2;
            size_t a0 = ob + (size_t)d * NL + ig;
            size_t a1 = ob + (size_t)(d + 1) * NL + ig;
            atth[a0]     = __float2half(o[mb][dt][0] * inv0);
            atth[a1]     = __float2half(o[mb][dt][1] * inv0);
            atth[a0 + 8] = __float2half(o[mb][dt][2] * inv1);
            atth[a1 + 8] = __float2half(o[mb][dt][3] * inv1);
        }
    }
}

// ---------------------------------------------------------------------------
extern "C" void kernel_launch(void* const* d_in, const int* in_sizes, int n_in,
                              void* d_out, int out_size)
{
    const float* x     = (const float*)d_in[0];
    const float* w_qkv = (const float*)d_in[1];
    const float* w_out = (const float*)d_in[2];
    const float* b_out = (const float*)d_in[3];
    float* out = (float*)d_out;

    __half *xh, *xl, *wqh, *woh, *qkvh, *atth;
    cudaGetSymbolAddress((void**)&xh,   g_xh);
    cudaGetSymbolAddress((void**)&xl,   g_xl);
    cudaGetSymbolAddress((void**)&wqh,  g_wqh);
    cudaGetSymbolAddress((void**)&woh,  g_woh);
    cudaGetSymbolAddress((void**)&qkvh, g_qkvh);
    cudaGetSymbolAddress((void**)&atth, g_atth);

    // 0) split x (hi+lo); weights hi-only transposed
    cvt_split<<<(NB * NC * NL / 4) / 256, 256>>>(
        (const float4*)x, (uint2*)xh, (uint2*)xl);
    cvt_hT<<<(NOQKV * NC) / 256, 256>>>(w_qkv, wqh, NOQKV, NC);
    cvt_hT<<<(NC * NHID) / 256, 256>>>(w_out, woh, NC, NHID);

    const int gsmem1 = 3 * 26112;          // 78336 (BLO=true)
    const int gsmem2 = 3 * 17408;          // 52224 (BLO=false)
    const int asmem  = 17408 + 2 * ASTG;   // 54272

    // 1) QKV projection: Wh * (Xh + Xl), hi-only split output
    cudaFuncSetAttribute((const void*)gemm_h<NOQKV, NC, false, true, true>,
                         cudaFuncAttributeMaxDynamicSharedMemorySize, gsmem1);
    gemm_h<NOQKV, NC, false, true, true>
        <<<dim3(NL / 128, NOQKV / 128, NB), 128, gsmem1>>>(
            wqh, xh, xl, nullptr, qkvh, nullptr);

    // 2) Attention (QK 1-MMA, PV 1-MMA)
    cudaFuncSetAttribute(attn_kernel,
                         cudaFuncAttributeMaxDynamicSharedMemorySize, asmem);
    attn_kernel<<<dim3(NL / 128, NH, NB), 128, asmem>>>(qkvh, atth);

    // 3) Output projection + bias: Wh * Att_h, fp32 out (1-MMA)
    cudaFuncSetAttribute((const void*)gemm_h<NC, NHID, true, false, false>,
                         cudaFuncAttributeMaxDynamicSharedMemorySize, gsmem2);
    gemm_h<NC, NHID, true, false, false>
        <<<dim3(NL / 128, NC / 128, NB), 128, gsmem2>>>(
            woh, atth, nullptr, b_out, nullptr, out);
}

// round 17
// speedup vs baseline: 2.5147x; 1.2415x over previous
#include <cuda_runtime.h>
#include <cuda_fp16.h>
#include <cstdint>

#define NB    8
#define NC    512
#define NL    2048
#define NH    8
#define ND    64
#define NHID  512
#define NOQKV 1536

// ---------------- device-global scratch (allocation-free) ----------------
__device__ __half g_xh[(size_t)NB * NC * NL];
__device__ __half g_wqh[(size_t)NC * NOQKV];    // [c][m] transposed
__device__ __half g_woh[(size_t)NHID * NC];     // [c][m] transposed
__device__ __half g_qkvh[(size_t)NB * NOQKV * NL];
__device__ __half g_atth[(size_t)NB * NHID * NL];

__device__ __forceinline__ float ex2(float x) {
    float y; asm("ex2.approx.f32 %0, %1;" : "=f"(y) : "f"(x)); return y;
}
// pack two fp32 -> f16x2 {low half = first arg}
__device__ __forceinline__ unsigned pckhf(float lo, float hi) {
    unsigned r; asm("cvt.rn.f16x2.f32 %0, %1, %2;" : "=r"(r) : "f"(hi), "f"(lo)); return r;
}
__device__ __forceinline__ void cpa16(unsigned s, const void* g) {
    asm volatile("cp.async.cg.shared.global [%0], [%1], 16;" :: "r"(s), "l"(g));
}
#define CPCOMMIT() asm volatile("cp.async.commit_group;")
#define CPWAIT(n)  asm volatile("cp.async.wait_group %0;" :: "n"(n))

#define LDSMX4(R0,R1,R2,R3,A) \
    asm volatile("ldmatrix.sync.aligned.m8n8.x4.shared.b16 {%0,%1,%2,%3}, [%4];" \
        : "=r"(R0),"=r"(R1),"=r"(R2),"=r"(R3) : "r"(A))
#define LDSMX4T(R0,R1,R2,R3,A) \
    asm volatile("ldmatrix.sync.aligned.m8n8.x4.trans.shared.b16 {%0,%1,%2,%3}, [%4];" \
        : "=r"(R0),"=r"(R1),"=r"(R2),"=r"(R3) : "r"(A))
// fp16 inputs, fp32 accumulate
#define MMAH(C,A0,A1,A2,A3,B0,B1) \
    asm("mma.sync.aligned.m16n8k16.row.col.f32.f16.f16.f32 " \
        "{%0,%1,%2,%3},{%4,%5,%6,%7},{%8,%9},{%0,%1,%2,%3};" \
        : "+f"((C)[0]),"+f"((C)[1]),"+f"((C)[2]),"+f"((C)[3]) \
        : "r"(A0),"r"(A1),"r"(A2),"r"(A3),"r"(B0),"r"(B1))

// ---------------------------------------------------------------------------
// fp32 -> fp16 conversion passes
// ---------------------------------------------------------------------------
__global__ void cvt_h(const float4* __restrict__ src, uint2* __restrict__ h)
{
    int i = blockIdx.x * blockDim.x + threadIdx.x;
    float4 f = src[i];
    uint2 hv;
    hv.x = pckhf(f.x, f.y);
    hv.y = pckhf(f.z, f.w);
    h[i] = hv;
}

// weights: fp32 [m][c] -> transposed fp16 [c][m]
__global__ void cvt_hT(const float* __restrict__ w,
                       __half* __restrict__ ht, int M, int C)
{
    int idx = blockIdx.x * blockDim.x + threadIdx.x;
    int m = idx / C, c = idx % C;
    ht[(size_t)c * M + m] = __float2half(w[idx]);
}

// ---------------------------------------------------------------------------
// fp16 GEMM (1 MMA/product), 3-stage cp.async pipeline, fp32 acc.
// Block 128x128, ktile 32, 128 threads = 4 warps (2x2), 64x64 per warp.
// ---------------------------------------------------------------------------
#define GSTG 17408   // bytes per stage: 2 arrays x 32 x 136 x 2B

template<int M, int K, bool HAS_BIAS, bool SPLIT_OUT>
__global__ __launch_bounds__(128) void gemm_h(
    const __half* __restrict__ Ah_g, const __half* __restrict__ Bh_g,
    const float* __restrict__ bias,
    __half* __restrict__ Yh, float* __restrict__ Yf)
{
    extern __shared__ __align__(16) unsigned char smg[];
    const int NT = K / 32;

    const int b  = blockIdx.z;
    const int m0 = blockIdx.y * 128;
    const int n0 = blockIdx.x * 128;

    const int tid  = threadIdx.x;
    const int lane = tid & 31;
    const int warp = tid >> 5;      // 0..3
    const int wm   = warp >> 1;     // m offset wm*64
    const int wn   = warp & 1;      // n offset wn*64

    unsigned sb = (unsigned)__cvta_generic_to_shared(smg);

    const unsigned offA = ((((lane >> 4) & 1) * 8 + (lane & 7)) * 272)
                        + (wm * 64 + ((lane >> 3) & 1) * 8) * 2;
    const unsigned offB = ((((lane >> 3) & 1) * 8 + (lane & 7)) * 272)
                        + (wn * 64 + ((lane >> 4) & 1) * 8) * 2;

    float acc[4][8][4];
    #pragma unroll
    for (int i = 0; i < 4; i++)
        #pragma unroll
        for (int j = 0; j < 8; j++)
            #pragma unroll
            for (int t = 0; t < 4; t++) acc[i][j][t] = 0.0f;

    auto issue = [&](int kt, int st) {
        unsigned base = sb + st * GSTG;
        int k0 = kt * 32;
        #pragma unroll
        for (int p = 0; p < 4; p++) {
            int q   = tid + p * 128;
            int row = q >> 4;
            int c8  = (q & 15) * 8;
            size_t ga = (size_t)(k0 + row) * M + m0 + c8;
            size_t gb = ((size_t)b * K + k0 + row) * NL + n0 + c8;
            unsigned so = row * 272 + c8 * 2;
            cpa16(base + so,          Ah_g + ga);
            cpa16(base + 8704 + so,   Bh_g + gb);
        }
    };

    issue(0, 0); CPCOMMIT();
    issue(1, 1); CPCOMMIT();

    for (int kt = 0; kt < NT; kt++) {
        CPWAIT(1);
        __syncthreads();
        if (kt + 2 < NT) issue(kt + 2, (kt + 2) % 3);
        CPCOMMIT();

        unsigned base = sb + (kt % 3) * GSTG;
        const unsigned SAH = base, SBH = base + 8704;

        #pragma unroll
        for (int kc = 0; kc < 2; kc++) {
            unsigned kb = kc * 16 * 272;
            unsigned bh[4][4];
            #pragma unroll
            for (int ng = 0; ng < 4; ng++)
                LDSMX4T(bh[ng][0], bh[ng][1], bh[ng][2], bh[ng][3],
                        SBH + offB + kb + ng * 32);
            #pragma unroll
            for (int mf = 0; mf < 4; mf++) {
                unsigned ah0,ah1,ah2,ah3;
                LDSMX4T(ah0,ah1,ah2,ah3, SAH + offA + kb + mf * 32);
                #pragma unroll
                for (int ng = 0; ng < 4; ng++) {
                    MMAH(acc[mf][2*ng],   ah0,ah1,ah2,ah3, bh[ng][0],bh[ng][1]);
                    MMAH(acc[mf][2*ng+1], ah0,ah1,ah2,ah3, bh[ng][2],bh[ng][3]);
                }
            }
        }
    }

    // ---- epilogue ----
    const int r0 = lane >> 2;
    const int cp = (lane & 3) * 2;
    #pragma unroll
    for (int mf = 0; mf < 4; mf++) {
        int ml = m0 + wm * 64 + mf * 16 + r0;
        float bv0 = 0.0f, bv1 = 0.0f;
        if (HAS_BIAS) { bv0 = bias[ml]; bv1 = bias[ml + 8]; }
        #pragma unroll
        for (int g = 0; g < 8; g++) {
            int n = n0 + wn * 64 + (g >> 1) * 16 + (g & 1) * 8 + cp;
            float* c = acc[mf][g];
            size_t a0 = ((size_t)b * M + ml) * NL + n;
            size_t a1 = a0 + (size_t)8 * NL;
            if (SPLIT_OUT) {
                *(unsigned*)(Yh + a0) = pckhf(c[0], c[1]);
                *(unsigned*)(Yh + a1) = pckhf(c[2], c[3]);
            } else {
                *(float2*)(Yf + a0) = make_float2(c[0] + bv0, c[1] + bv0);
                *(float2*)(Yf + a1) = make_float2(c[2] + bv1, c[3] + bv1);
            }
        }
    }
}

// ---------------------------------------------------------------------------
// Flash attention, pure-fp16 operands: S = qh*kh [1 MMA], O += ph*vh [1 MMA].
// BM=128 queries, 4 warps x m32 rows, BN=64 keys, 2-stage cp.async K/V.
// smem: QH 17408 + 2 stages x 18432 = 54272 B.
// ---------------------------------------------------------------------------
#define ASTG 18432

__global__ __launch_bounds__(128) void attn_kernel(
    const __half* __restrict__ qkvh, __half* __restrict__ atth)
{
    extern __shared__ __align__(16) unsigned char sma[];

    const int tid  = threadIdx.x;
    const int lane = tid & 31;
    const int warp = tid >> 5;
    const int i0 = blockIdx.x * 128;
    const int h  = blockIdx.y;
    const int b  = blockIdx.z;

    const size_t base = ((size_t)b * NOQKV + h * ND) * NL;
    const __half* qph = qkvh + base;
    const __half* kph = qph + (size_t)NHID * NL;
    const __half* vph = qph + (size_t)2 * NHID * NL;

    unsigned sb = (unsigned)__cvta_generic_to_shared(sma);
    const unsigned QH = sb, KV0 = sb + 17408;

    const unsigned offQ = (((lane >> 4) & 1) * 8 + (lane & 7)) * 272
                        + (warp * 32 + ((lane >> 3) & 1) * 8) * 2;
    const unsigned offK = (((lane >> 3) & 1) * 8 + (lane & 7)) * 144
                        + (((lane >> 4) & 1) * 8) * 2;
    const unsigned offV = (((lane >> 4) & 1) * 8 + (lane & 7)) * 144
                        + (((lane >> 3) & 1) * 8) * 2;

    const float SC = 0.125f * 1.44269504f;

    auto issueKV = [&](int j0, int st) {
        unsigned kb = KV0 + st * ASTG;
        #pragma unroll
        for (int p = 0; p < 4; p++) {
            int q   = tid + p * 128;
            int row = q >> 3;
            int col = (q & 7) * 8;
            unsigned so = row * 144 + col * 2;
            size_t g = (size_t)row * NL + j0 + col;
            cpa16(kb + so,          kph + g);
            cpa16(kb + 9216 + so,   vph + g);
        }
    };

    {
        #pragma unroll
        for (int p = 0; p < 8; p++) {
            int q = tid + p * 128;
            int r = q >> 4, c16 = (q & 15) * 8;
            unsigned so = r * 272 + c16 * 2;
            cpa16(QH + so, qph + (size_t)r * NL + i0 + c16);
        }
        issueKV(0, 0);
        CPCOMMIT();
    }

    float o[2][8][4];
    float mm[2][2], ll[2][2];
    #pragma unroll
    for (int mb = 0; mb < 2; mb++) {
        mm[mb][0] = -1e30f; mm[mb][1] = -1e30f;
        ll[mb][0] = 0.0f;   ll[mb][1] = 0.0f;
        #pragma unroll
        for (int t = 0; t < 8; t++)
            #pragma unroll
            for (int c = 0; c < 4; c++) o[mb][t][c] = 0.0f;
    }

    for (int jt = 0; jt < 32; jt++) {
        if (jt + 1 < 32) issueKV((jt + 1) * 64, (jt + 1) & 1);
        CPCOMMIT();
        if (jt == 31) { CPWAIT(0); } else { CPWAIT(1); }
        __syncthreads();

        unsigned kb = KV0 + (jt & 1) * ASTG;
        const unsigned KH = kb, VH = kb + 9216;

        // ---- S = qh * kh ----
        float s[2][8][4];
        #pragma unroll
        for (int mb = 0; mb < 2; mb++)
            #pragma unroll
            for (int t = 0; t < 8; t++)
                #pragma unroll
                for (int c = 0; c < 4; c++) s[mb][t][c] = 0.0f;

        #pragma unroll
        for (int kc = 0; kc < 4; kc++) {
            unsigned kcq = kc * 16 * 272;
            unsigned kck = kc * 16 * 144;
            unsigned qa[2][4];
            LDSMX4T(qa[0][0],qa[0][1],qa[0][2],qa[0][3], QH + offQ + kcq);
            LDSMX4T(qa[1][0],qa[1][1],qa[1][2],qa[1][3], QH + offQ + kcq + 32);
            #pragma unroll
            for (int p = 0; p < 4; p++) {
                unsigned nb = p * 32;
                unsigned h0,h1,h2,h3;
                LDSMX4T(h0,h1,h2,h3, KH + offK + kck + nb);
                #pragma unroll
                for (int mb = 0; mb < 2; mb++) {
                    MMAH(s[mb][2*p],   qa[mb][0],qa[mb][1],qa[mb][2],qa[mb][3], h0,h1);
                    MMAH(s[mb][2*p+1], qa[mb][0],qa[mb][1],qa[mb][2],qa[mb][3], h2,h3);
                }
            }
        }

        // ---- online softmax + P hi fragments ----
        unsigned pah[2][4][4];
        #pragma unroll
        for (int mb = 0; mb < 2; mb++) {
            float mx0 = -1e30f, mx1 = -1e30f;
            #pragma unroll
            for (int t = 0; t < 8; t++) {
                s[mb][t][0] *= SC; s[mb][t][1] *= SC;
                s[mb][t][2] *= SC; s[mb][t][3] *= SC;
                mx0 = fmaxf(mx0, fmaxf(s[mb][t][0], s[mb][t][1]));
                mx1 = fmaxf(mx1, fmaxf(s[mb][t][2], s[mb][t][3]));
            }
            mx0 = fmaxf(mx0, __shfl_xor_sync(0xffffffffu, mx0, 1));
            mx0 = fmaxf(mx0, __shfl_xor_sync(0xffffffffu, mx0, 2));
            mx1 = fmaxf(mx1, __shfl_xor_sync(0xffffffffu, mx1, 1));
            mx1 = fmaxf(mx1, __shfl_xor_sync(0xffffffffu, mx1, 2));
            float mn0 = fmaxf(mm[mb][0], mx0), mn1 = fmaxf(mm[mb][1], mx1);
            float c0 = ex2(mm[mb][0] - mn0),   c1 = ex2(mm[mb][1] - mn1);
            mm[mb][0] = mn0; mm[mb][1] = mn1;

            float rs0 = 0.0f, rs1 = 0.0f;
            #pragma unroll
            for (int t = 0; t < 8; t++) {
                s[mb][t][0] = ex2(s[mb][t][0] - mn0);
                s[mb][t][1] = ex2(s[mb][t][1] - mn0);
                s[mb][t][2] = ex2(s[mb][t][2] - mn1);
                s[mb][t][3] = ex2(s[mb][t][3] - mn1);
                rs0 += s[mb][t][0] + s[mb][t][1];
                rs1 += s[mb][t][2] + s[mb][t][3];
            }
            ll[mb][0] = ll[mb][0] * c0 + rs0;
            ll[mb][1] = ll[mb][1] * c1 + rs1;
            #pragma unroll
            for (int t = 0; t < 8; t++) {
                o[mb][t][0] *= c0; o[mb][t][1] *= c0;
                o[mb][t][2] *= c1; o[mb][t][3] *= c1;
            }
            #pragma unroll
            for (int c = 0; c < 4; c++) {
                int A = 2 * c, B = 2 * c + 1;
                pah[mb][c][0] = pckhf(s[mb][A][0], s[mb][A][1]);
                pah[mb][c][1] = pckhf(s[mb][A][2], s[mb][A][3]);
                pah[mb][c][2] = pckhf(s[mb][B][0], s[mb][B][1]);
                pah[mb][c][3] = pckhf(s[mb][B][2], s[mb][B][3]);
            }
        }

        // ---- O += ph * vh ----
        #pragma unroll
        for (int c = 0; c < 4; c++) {
            unsigned jb = c * 32;
            #pragma unroll
            for (int p = 0; p < 4; p++) {
                unsigned db = p * 2304;
                unsigned h0,h1,h2,h3;
                LDSMX4(h0,h1,h2,h3, VH + offV + db + jb);
                #pragma unroll
                for (int mb = 0; mb < 2; mb++) {
                    MMAH(o[mb][2*p],   pah[mb][c][0],pah[mb][c][1],pah[mb][c][2],pah[mb][c][3], h0,h1);
                    MMAH(o[mb][2*p+1], pah[mb][c][0],pah[mb][c][1],pah[mb][c][2],pah[mb][c][3], h2,h3);
                }
            }
        }
        __syncthreads();
    }

    // ---- finalize: write att hi [ch][l] ----
    const size_t ob = ((size_t)b * NHID + h * ND) * NL;
    #pragma unroll
    for (int mb = 0; mb < 2; mb++) {
        float l0 = ll[mb][0], l1 = ll[mb][1];
        l0 += __shfl_xor_sync(0xffffffffu, l0, 1);
        l0 += __shfl_xor_sync(0xffffffffu, l0, 2);
        l1 += __shfl_xor_sync(0xffffffffu, l1, 1);
        l1 += __shfl_xor_sync(0xffffffffu, l1, 2);
        float inv0 = __fdividef(1.0f, l0);
        float inv1 = __fdividef(1.0f, l1);

        int ig = i0 + warp * 32 + mb * 16 + (lane >> 2);
        #pragma unroll
        for (int dt = 0; dt < 8; dt++) {
            int d = dt * 8 + (lane & 3) * 2;
            size_t a0 = ob + (size_t)d * NL + ig;
            size_t a1 = ob + (size_t)(d + 1) * NL + ig;
            atth[a0]     = __float2half(o[mb][dt][0] * inv0);
            atth[a1]     = __float2half(o[mb][dt][1] * inv0);
            atth[a0 + 8] = __float2half(o[mb][dt][2] * inv1);
            atth[a1 + 8] = __float2half(o[mb][dt][3] * inv1);
        }
    }
}

// ---------------------------------------------------------------------------
extern "C" void kernel_launch(void* const* d_in, const int* in_sizes, int n_in,
                              void* d_out, int out_size)
{
    const float* x     = (const float*)d_in[0];
    const float* w_qkv = (const float*)d_in[1];
    const float* w_out = (const float*)d_in[2];
    const float* b_out = (const float*)d_in[3];
    float* out = (float*)d_out;

    __half *xh, *wqh, *woh, *qkvh, *atth;
    cudaGetSymbolAddress((void**)&xh,   g_xh);
    cudaGetSymbolAddress((void**)&wqh,  g_wqh);
    cudaGetSymbolAddress((void**)&woh,  g_woh);
    cudaGetSymbolAddress((void**)&qkvh, g_qkvh);
    cudaGetSymbolAddress((void**)&atth, g_atth);

    // 0) convert x and weights to fp16 (weights transposed)
    cvt_h<<<(NB * NC * NL / 4) / 256, 256>>>((const float4*)x, (uint2*)xh);
    cvt_hT<<<(NOQKV * NC) / 256, 256>>>(w_qkv, wqh, NOQKV, NC);
    cvt_hT<<<(NC * NHID) / 256, 256>>>(w_out, woh, NC, NHID);

    const int gsmem = 3 * GSTG;            // 52224
    const int asmem = 17408 + 2 * ASTG;    // 54272

    // 1) QKV projection (1-MMA)
    cudaFuncSetAttribute((const void*)gemm_h<NOQKV, NC, false, true>,
                         cudaFuncAttributeMaxDynamicSharedMemorySize, gsmem);
    gemm_h<NOQKV, NC, false, true>
        <<<dim3(NL / 128, NOQKV / 128, NB), 128, gsmem>>>(
            wqh, xh, nullptr, qkvh, nullptr);

    // 2) Attention (QK 1-MMA, PV 1-MMA)
    cudaFuncSetAttribute(attn_kernel,
                         cudaFuncAttributeMaxDynamicSharedMemorySize, asmem);
    attn_kernel<<<dim3(NL / 128, NH, NB), 128, asmem>>>(qkvh, atth);

    // 3) Output projection + bias (1-MMA)
    cudaFuncSetAttribute((const void*)gemm_h<NC, NHID, true, false>,
                         cudaFuncAttributeMaxDynamicSharedMemorySize, gsmem);
    gemm_h<NC, NHID, true, false>
        <<<dim3(NL / 128, NC / 128, NB), 128, gsmem>>>(
            woh, atth, b_out, nullptr, out);
}